// round 8
// baseline (speedup 1.0000x reference)
#include <cuda_runtime.h>
#include <cuda_bf16.h>
#include <cstdint>

// ---------------------------------------------------------------------------
// Problem constants
// ---------------------------------------------------------------------------
constexpr int DIM  = 1024;
constexpr int ROWS = 4096;   // BATCH * SEQ

// ---------------------------------------------------------------------------
// Device scratch (allocation-free per harness rules)
// fp32 operands split into bf16 (hi, lo):  v ~= hi + lo, |err| ~ 2^-17 |v|
// ---------------------------------------------------------------------------
__device__ __align__(16) __nv_bfloat16 g_xh[ROWS * DIM];
__device__ __align__(16) __nv_bfloat16 g_xl[ROWS * DIM];
__device__ __align__(16) __nv_bfloat16 g_wvh[DIM * DIM];
__device__ __align__(16) __nv_bfloat16 g_wvl[DIM * DIM];
__device__ __align__(16) __nv_bfloat16 g_wph[DIM * DIM];
__device__ __align__(16) __nv_bfloat16 g_wpl[DIM * DIM];
__device__ __align__(16) __nv_bfloat16 g_mh[DIM * DIM];   // M = Wv @ Wp (hi)
__device__ __align__(16) __nv_bfloat16 g_ml[DIM * DIM];   // M (lo)
__device__ float g_c[DIM];                                 // fused bias
constexpr int KSLICES = 16;
__device__ float g_cpart[KSLICES * DIM];                   // bias partials

// ---------------------------------------------------------------------------
// Helpers
// ---------------------------------------------------------------------------
__device__ __forceinline__ uint32_t smem_u32(const void* p) {
    uint32_t a;
    asm("{ .reg .u64 t; cvta.to.shared.u64 t, %1; cvt.u32.u64 %0, t; }" : "=r"(a) : "l"(p));
    return a;
}
__device__ __forceinline__ void cp16(uint32_t dst, const void* src) {
    asm volatile("cp.async.cg.shared.global [%0], [%1], 16;" :: "r"(dst), "l"(src));
}
#define CP_COMMIT() asm volatile("cp.async.commit_group;" ::: "memory")

__device__ __forceinline__ void mma_bf16(float d[4], const uint32_t a[4], const uint32_t b[2]) {
    asm volatile(
        "mma.sync.aligned.m16n8k16.row.col.f32.bf16.bf16.f32 "
        "{%0,%1,%2,%3}, {%4,%5,%6,%7}, {%8,%9}, {%0,%1,%2,%3};"
        : "+f"(d[0]), "+f"(d[1]), "+f"(d[2]), "+f"(d[3])
        : "r"(a[0]), "r"(a[1]), "r"(a[2]), "r"(a[3]), "r"(b[0]), "r"(b[1]));
}

// ---------------------------------------------------------------------------
// Split kernel: fp32 [rows x cols] (leading dim ld) -> bf16 hi/lo (dense)
// ---------------------------------------------------------------------------
__global__ void split_kernel(const float* __restrict__ in, int ld,
                             __nv_bfloat16* __restrict__ hi,
                             __nv_bfloat16* __restrict__ lo,
                             int rows, int cols)
{
    const int idx = blockIdx.x * blockDim.x + threadIdx.x;   // one float4
    const int c4 = cols >> 2;
    if (idx >= rows * c4) return;
    const int r = idx / c4;
    const int c = (idx - r * c4) << 2;
    float4 v = *reinterpret_cast<const float4*>(in + (size_t)r * ld + c);
    __nv_bfloat16 hx = __float2bfloat16(v.x), hy = __float2bfloat16(v.y);
    __nv_bfloat16 hz = __float2bfloat16(v.z), hw = __float2bfloat16(v.w);
    __nv_bfloat16 lx = __float2bfloat16(v.x - __bfloat162float(hx));
    __nv_bfloat16 ly = __float2bfloat16(v.y - __bfloat162float(hy));
    __nv_bfloat16 lz = __float2bfloat16(v.z - __bfloat162float(hz));
    __nv_bfloat16 lw = __float2bfloat16(v.w - __bfloat162float(hw));
    __nv_bfloat162* ph = reinterpret_cast<__nv_bfloat162*>(hi + (size_t)r * cols + c);
    ph[0] = __nv_bfloat162(hx, hy);  ph[1] = __nv_bfloat162(hz, hw);
    __nv_bfloat162* pl = reinterpret_cast<__nv_bfloat162*>(lo + (size_t)r * cols + c);
    pl[0] = __nv_bfloat162(lx, ly);  pl[1] = __nv_bfloat162(lz, lw);
}

// ---------------------------------------------------------------------------
// HMMA GEMM with fp32 emulation via bf16 split-3 over K' = 3K sections:
//   sec0: Ah*Bh, sec1: Ah*Bl, sec2: Al*Bh   (AlBl dropped, ~2^-16)
// Templated on MI (warp M-tiles): CTA tile = (MI*32) x 128, 8 warps as 2x4,
// warp tile (MI*16) x 32. KC=64 chunks, cp.async 3-stage, 1 barrier/chunk.
// Output: fp32 C (+ bias) if Cf != nullptr, else split bf16 (Chi, Clo).
// ---------------------------------------------------------------------------
constexpr int BN = 128, KC = 64;
constexpr int NSTAGE = 3;
constexpr int APITCH = 144;                 // 128B data + 16B pad
constexpr int BPITCH = 272;                 // 256B data + 16B pad
constexpr int B_BYTES = KC * BPITCH;        // 17408

// Compile-time config usable from both host and device code
template<int MI>
struct Cfg {
    static constexpr int A_BYTES     = MI * 32 * APITCH;
    static constexpr int STAGE_BYTES = A_BYTES + B_BYTES;
    static constexpr int SMEMT       = NSTAGE * STAGE_BYTES;
};
// MI=4: 107520 B (2 CTA/SM).  MI=2: 79872 B.

template<int MI>
__device__ __forceinline__ void issue_chunk(
    uint32_t sbase, int st,
    const __nv_bfloat16* Aptr, const __nv_bfloat16* Bptr,
    int lda, int ldb, int m0, int n0, int k0, int tid)
{
    const uint32_t sA = sbase + st * Cfg<MI>::STAGE_BYTES;
    const uint32_t sB = sA + Cfg<MI>::A_BYTES;
    const int arow = tid >> 3, ack = tid & 7;
    const int brow = tid >> 4, bck = tid & 15;
    #pragma unroll
    for (int p = 0; p < MI; p++) {
        const int r = arow + p * 32;
        cp16(sA + r * APITCH + ack * 16,
             Aptr + (size_t)(m0 + r) * lda + k0 + ack * 8);
    }
    #pragma unroll
    for (int p = 0; p < 4; p++) {
        const int kr = brow + p * 16;
        cp16(sB + kr * BPITCH + bck * 16,
             Bptr + (size_t)(k0 + kr) * ldb + n0 + bck * 8);
    }
    CP_COMMIT();
}

template<int MI>
__global__ __launch_bounds__(256, 2)
void gemm_bf16x3(const __nv_bfloat16* __restrict__ Ah, const __nv_bfloat16* __restrict__ Al, int lda,
                 const __nv_bfloat16* __restrict__ Bh, const __nv_bfloat16* __restrict__ Bl, int ldb,
                 float* __restrict__ Cf, const float* __restrict__ bias,
                 __nv_bfloat16* __restrict__ Chi, __nv_bfloat16* __restrict__ Clo,
                 int ldc, int K)
{
    extern __shared__ char smem[];
    const uint32_t sbase = smem_u32(smem);
    const int tid  = threadIdx.x;
    const int wid  = tid >> 5;
    const int lane = tid & 31;
    const int wr   = wid >> 2;     // 0..1  (warp row: MI*16 rows each)
    const int wc   = wid & 3;      // 0..3  (warp col: 32 cols each)
    const int m0   = blockIdx.y * (MI * 32);
    const int n0   = blockIdx.x * BN;

    const int NSEC = K / KC;       // chunks per section
    const int NCH  = 3 * NSEC;

    auto chunk_src = [&](int ch, const __nv_bfloat16*& Ap, const __nv_bfloat16*& Bp, int& k0) {
        const int sec = ch / NSEC;
        const int kk  = ch - sec * NSEC;
        Ap = (sec < 2) ? Ah : Al;
        Bp = (sec == 1) ? Bl : Bh;
        k0 = kk * KC;
    };

    float d[MI][4][4];
    #pragma unroll
    for (int mi = 0; mi < MI; mi++)
        #pragma unroll
        for (int ni = 0; ni < 4; ni++)
            #pragma unroll
            for (int r = 0; r < 4; r++) d[mi][ni][r] = 0.0f;

    // Prologue: stages 0 .. NSTAGE-2
    #pragma unroll
    for (int s = 0; s < NSTAGE - 1; s++) {
        const __nv_bfloat16 *Ap, *Bp; int k0;
        chunk_src(s, Ap, Bp, k0);
        issue_chunk<MI>(sbase, s, Ap, Bp, lda, ldb, m0, n0, k0, tid);
    }

    for (int ch = 0; ch < NCH; ch++) {
        // Ensure chunk ch's group has landed
        if (ch < NCH - 1) asm volatile("cp.async.wait_group 1;" ::: "memory");
        else              asm volatile("cp.async.wait_group 0;" ::: "memory");
        // One barrier: data visible + all warps done computing chunk ch-1,
        // so the stage written below ((ch-1)%NSTAGE) is free.
        __syncthreads();

        if (ch + NSTAGE - 1 < NCH) {
            const __nv_bfloat16 *Ap, *Bp; int k0;
            chunk_src(ch + NSTAGE - 1, Ap, Bp, k0);
            issue_chunk<MI>(sbase, (ch + NSTAGE - 1) % NSTAGE, Ap, Bp, lda, ldb, m0, n0, k0, tid);
        }

        const uint32_t sA = sbase + (ch % NSTAGE) * Cfg<MI>::STAGE_BYTES;
        const uint32_t sB = sA + Cfg<MI>::A_BYTES;

        #pragma unroll
        for (int ki = 0; ki < KC / 16; ki++) {
            uint32_t a[MI][4];
            #pragma unroll
            for (int mi = 0; mi < MI; mi++) {
                const uint32_t addr = sA
                    + (uint32_t)(wr * (MI * 16) + mi * 16 + (lane & 15)) * APITCH
                    + (uint32_t)((lane >> 4) * 8 + ki * 16) * 2;
                asm volatile("ldmatrix.sync.aligned.m8n8.x4.shared.b16 {%0,%1,%2,%3}, [%4];"
                    : "=r"(a[mi][0]), "=r"(a[mi][1]), "=r"(a[mi][2]), "=r"(a[mi][3])
                    : "r"(addr));
            }
            uint32_t b[4][2];
            #pragma unroll
            for (int t = 0; t < 2; t++) {
                const uint32_t addr = sB
                    + (uint32_t)(ki * 16 + (lane & 15)) * BPITCH
                    + (uint32_t)(wc * 32 + t * 16 + (lane >> 4) * 8) * 2;
                uint32_t r0, r1, r2, r3;
                asm volatile("ldmatrix.sync.aligned.m8n8.x4.trans.shared.b16 {%0,%1,%2,%3}, [%4];"
                    : "=r"(r0), "=r"(r1), "=r"(r2), "=r"(r3) : "r"(addr));
                b[2 * t][0] = r0;  b[2 * t][1] = r1;
                b[2 * t + 1][0] = r2;  b[2 * t + 1][1] = r3;
            }
            #pragma unroll
            for (int mi = 0; mi < MI; mi++)
                #pragma unroll
                for (int ni = 0; ni < 4; ni++)
                    mma_bf16(d[mi][ni], a[mi], b[ni]);
        }
    }

    // ---- Epilogue ----
    #pragma unroll
    for (int mi = 0; mi < MI; mi++) {
        const int mrow = m0 + wr * (MI * 16) + mi * 16 + (lane >> 2);
        #pragma unroll
        for (int ni = 0; ni < 4; ni++) {
            const int ncol = n0 + wc * 32 + ni * 8 + (lane & 3) * 2;
            #pragma unroll
            for (int half = 0; half < 2; half++) {     // rows mrow, mrow+8
                const int r = mrow + half * 8;
                float v0 = d[mi][ni][half * 2 + 0];
                float v1 = d[mi][ni][half * 2 + 1];
                if (Cf != nullptr) {
                    if (bias != nullptr) { v0 += bias[ncol]; v1 += bias[ncol + 1]; }
                    float2 o; o.x = v0; o.y = v1;
                    *reinterpret_cast<float2*>(Cf + (size_t)r * ldc + ncol) = o;
                } else {
                    __nv_bfloat16 h0 = __float2bfloat16(v0);
                    __nv_bfloat16 h1 = __float2bfloat16(v1);
                    __nv_bfloat16 l0 = __float2bfloat16(v0 - __bfloat162float(h0));
                    __nv_bfloat16 l1 = __float2bfloat16(v1 - __bfloat162float(h1));
                    *reinterpret_cast<__nv_bfloat162*>(Chi + (size_t)r * ldc + ncol) = __nv_bfloat162(h0, h1);
                    *reinterpret_cast<__nv_bfloat162*>(Clo + (size_t)r * ldc + ncol) = __nv_bfloat162(l0, l1);
                }
            }
        }
    }
}

// ---------------------------------------------------------------------------
// Fused bias, parallel: c[j] = sum_k b_v[k] * w_proj[k, j] + b_proj[j]
// ---------------------------------------------------------------------------
__global__ void bias_partial_kernel(const float* __restrict__ b_qkv,
                                    const float* __restrict__ w_proj)
{
    const int j  = blockIdx.x * blockDim.x + threadIdx.x;   // 0..DIM-1
    const int s  = blockIdx.y;                              // k-slice
    const int kb = s * (DIM / KSLICES);
    float acc = 0.0f;
    #pragma unroll 8
    for (int k = 0; k < DIM / KSLICES; k++)
        acc += b_qkv[2 * DIM + kb + k] * w_proj[(size_t)(kb + k) * DIM + j];
    g_cpart[s * DIM + j] = acc;
}

__global__ void bias_reduce_kernel(const float* __restrict__ b_proj)
{
    const int j = blockIdx.x * blockDim.x + threadIdx.x;
    if (j >= DIM) return;
    float acc = b_proj[j];
    #pragma unroll
    for (int s = 0; s < KSLICES; s++) acc += g_cpart[s * DIM + j];
    g_c[j] = acc;
}

// ---------------------------------------------------------------------------
// kernel_launch  (serial, single default stream — known-good capture shape)
// Math: softmax rows sum to 1 and the reference's final einsum contracts k
// over attn only, so out == v. Head permutations cancel on flattened layout:
//   out = x @ (w_qkv[:,2C:3C] @ w_proj) + (b_qkv[2C:3C] @ w_proj + b_proj)
// ---------------------------------------------------------------------------
extern "C" void kernel_launch(void* const* d_in, const int* in_sizes, int n_in,
                              void* d_out, int out_size)
{
    const float* x      = (const float*)d_in[0];  // [4096, 1024]
    const float* w_qkv  = (const float*)d_in[1];  // [1024, 3072]
    const float* b_qkv  = (const float*)d_in[2];  // [3072]
    const float* w_proj = (const float*)d_in[3];  // [1024, 1024]
    const float* b_proj = (const float*)d_in[4];  // [1024]
    float* out = (float*)d_out;                   // [4096, 1024]

    __nv_bfloat16 *xh, *xl, *wvh, *wvl, *wph, *wpl, *mh, *ml;
    float* pc;
    cudaGetSymbolAddress((void**)&xh,  g_xh);
    cudaGetSymbolAddress((void**)&xl,  g_xl);
    cudaGetSymbolAddress((void**)&wvh, g_wvh);
    cudaGetSymbolAddress((void**)&wvl, g_wvl);
    cudaGetSymbolAddress((void**)&wph, g_wph);
    cudaGetSymbolAddress((void**)&wpl, g_wpl);
    cudaGetSymbolAddress((void**)&mh,  g_mh);
    cudaGetSymbolAddress((void**)&ml,  g_ml);
    cudaGetSymbolAddress((void**)&pc,  g_c);

    cudaFuncSetAttribute(gemm_bf16x3<4>, cudaFuncAttributeMaxDynamicSharedMemorySize, Cfg<4>::SMEMT);
    cudaFuncSetAttribute(gemm_bf16x3<2>, cudaFuncAttributeMaxDynamicSharedMemorySize, Cfg<2>::SMEMT);

    // 1) Split conversions
    split_kernel<<<(DIM * DIM / 4 + 255) / 256, 256>>>(w_qkv + 2 * DIM, 3 * DIM, wvh, wvl, DIM, DIM);
    split_kernel<<<(DIM * DIM / 4 + 255) / 256, 256>>>(w_proj, DIM, wph, wpl, DIM, DIM);
    split_kernel<<<(ROWS * DIM / 4 + 255) / 256, 256>>>(x, DIM, xh, xl, ROWS, DIM);

    // 2) fused bias (parallel two-phase, no atomics)
    {
        dim3 grid(DIM / 256, KSLICES);
        bias_partial_kernel<<<grid, 256>>>(b_qkv, w_proj);
        bias_reduce_kernel<<<DIM / 256, 256>>>(b_proj);
    }

    // 3) GEMM1: M = Wv @ Wp  (MI=2 -> BM=64, 8 x 16 = 128 CTAs, bf16 hi/lo direct)
    {
        dim3 grid(DIM / BN, DIM / 64);
        gemm_bf16x3<2><<<grid, 256, Cfg<2>::SMEMT>>>(wvh, wvl, DIM, wph, wpl, DIM,
                                                     nullptr, nullptr, mh, ml, DIM, DIM);
    }

    // 4) GEMM2: out = x @ M + c  (MI=4 -> BM=128, 8 x 32 = 256 CTAs)
    {
        dim3 grid(DIM / BN, ROWS / 128);
        gemm_bf16x3<4><<<grid, 256, Cfg<4>::SMEMT>>>(xh, xl, DIM, mh, ml, DIM,
                                                     out, pc, nullptr, nullptr, DIM, DIM);
    }
}

// round 10
// speedup vs baseline: 1.2759x; 1.2759x over previous
#include <cuda_runtime.h>
#include <cuda_bf16.h>
#include <cuda_fp16.h>
#include <cstdint>

// ---------------------------------------------------------------------------
// Problem constants
// ---------------------------------------------------------------------------
constexpr int DIM  = 1024;
constexpr int ROWS = 4096;   // BATCH * SEQ

// ---------------------------------------------------------------------------
// Device scratch (allocation-free per harness rules)
// x split into fp16 (hi, lo): x ~= xh + xl, |err| ~ 2^-23 |x|
// weights split into bf16 (hi, lo) for the 3-term weight-fusion GEMM.
// M stored as a single fp16 buffer (error 2^-12, dominates final rel_err).
// ---------------------------------------------------------------------------
__device__ __align__(16) __half        g_xh[ROWS * DIM];
__device__ __align__(16) __half        g_xl[ROWS * DIM];
__device__ __align__(16) __nv_bfloat16 g_wvh[DIM * DIM];
__device__ __align__(16) __nv_bfloat16 g_wvl[DIM * DIM];
__device__ __align__(16) __nv_bfloat16 g_wph[DIM * DIM];
__device__ __align__(16) __nv_bfloat16 g_wpl[DIM * DIM];
__device__ __align__(16) __half        g_mh[DIM * DIM];   // M = Wv @ Wp (fp16)
__device__ __align__(16) float g_p0[DIM * DIM];           // split-K partial 0
__device__ __align__(16) float g_p1[DIM * DIM];           // split-K partial 1
__device__ float g_c[DIM];                                 // fused bias
constexpr int KSLICES = 16;
__device__ float g_cpart[KSLICES * DIM];                   // bias partials

// ---------------------------------------------------------------------------
// Helpers
// ---------------------------------------------------------------------------
__device__ __forceinline__ uint32_t smem_u32(const void* p) {
    uint32_t a;
    asm("{ .reg .u64 t; cvta.to.shared.u64 t, %1; cvt.u32.u64 %0, t; }" : "=r"(a) : "l"(p));
    return a;
}
__device__ __forceinline__ void cp16(uint32_t dst, const void* src) {
    asm volatile("cp.async.cg.shared.global [%0], [%1], 16;" :: "r"(dst), "l"(src));
}
#define CP_COMMIT() asm volatile("cp.async.commit_group;" ::: "memory")

template<bool F16>
__device__ __forceinline__ void mma16(float d[4], const uint32_t a[4], const uint32_t b[2]) {
    if (F16) {
        asm volatile(
            "mma.sync.aligned.m16n8k16.row.col.f32.f16.f16.f32 "
            "{%0,%1,%2,%3}, {%4,%5,%6,%7}, {%8,%9}, {%0,%1,%2,%3};"
            : "+f"(d[0]), "+f"(d[1]), "+f"(d[2]), "+f"(d[3])
            : "r"(a[0]), "r"(a[1]), "r"(a[2]), "r"(a[3]), "r"(b[0]), "r"(b[1]));
    } else {
        asm volatile(
            "mma.sync.aligned.m16n8k16.row.col.f32.bf16.bf16.f32 "
            "{%0,%1,%2,%3}, {%4,%5,%6,%7}, {%8,%9}, {%0,%1,%2,%3};"
            : "+f"(d[0]), "+f"(d[1]), "+f"(d[2]), "+f"(d[3])
            : "r"(a[0]), "r"(a[1]), "r"(a[2]), "r"(a[3]), "r"(b[0]), "r"(b[1]));
    }
}

// ---------------------------------------------------------------------------
// Split kernels
// ---------------------------------------------------------------------------
__global__ void split_bf16_kernel(const float* __restrict__ in, int ld,
                                  __nv_bfloat16* __restrict__ hi,
                                  __nv_bfloat16* __restrict__ lo,
                                  int rows, int cols)
{
    const int idx = blockIdx.x * blockDim.x + threadIdx.x;
    const int c4 = cols >> 2;
    if (idx >= rows * c4) return;
    const int r = idx / c4;
    const int c = (idx - r * c4) << 2;
    float4 v = *reinterpret_cast<const float4*>(in + (size_t)r * ld + c);
    __nv_bfloat16 hx = __float2bfloat16(v.x), hy = __float2bfloat16(v.y);
    __nv_bfloat16 hz = __float2bfloat16(v.z), hw = __float2bfloat16(v.w);
    __nv_bfloat16 lx = __float2bfloat16(v.x - __bfloat162float(hx));
    __nv_bfloat16 ly = __float2bfloat16(v.y - __bfloat162float(hy));
    __nv_bfloat16 lz = __float2bfloat16(v.z - __bfloat162float(hz));
    __nv_bfloat16 lw = __float2bfloat16(v.w - __bfloat162float(hw));
    __nv_bfloat162* ph = reinterpret_cast<__nv_bfloat162*>(hi + (size_t)r * cols + c);
    ph[0] = __nv_bfloat162(hx, hy);  ph[1] = __nv_bfloat162(hz, hw);
    __nv_bfloat162* pl = reinterpret_cast<__nv_bfloat162*>(lo + (size_t)r * cols + c);
    pl[0] = __nv_bfloat162(lx, ly);  pl[1] = __nv_bfloat162(lz, lw);
}

__global__ void split_f16_kernel(const float* __restrict__ in,
                                 __half* __restrict__ hi,
                                 __half* __restrict__ lo,
                                 int n4)
{
    const int idx = blockIdx.x * blockDim.x + threadIdx.x;
    if (idx >= n4) return;
    const int c = idx << 2;
    float4 v = *reinterpret_cast<const float4*>(in + c);
    __half hx = __float2half_rn(v.x), hy = __float2half_rn(v.y);
    __half hz = __float2half_rn(v.z), hw = __float2half_rn(v.w);
    __half lx = __float2half_rn(v.x - __half2float(hx));
    __half ly = __float2half_rn(v.y - __half2float(hy));
    __half lz = __float2half_rn(v.z - __half2float(hz));
    __half lw = __float2half_rn(v.w - __half2float(hw));
    __half2* ph = reinterpret_cast<__half2*>(hi + c);
    ph[0] = __half2(hx, hy);  ph[1] = __half2(hz, hw);
    __half2* pl = reinterpret_cast<__half2*>(lo + c);
    pl[0] = __half2(lx, ly);  pl[1] = __half2(lz, lw);
}

// Combine split-K partials -> single fp16 M
__global__ void combine_f16_kernel(__half* __restrict__ mh)
{
    const int idx = blockIdx.x * blockDim.x + threadIdx.x;
    if (idx >= DIM * DIM / 4) return;
    const int c = idx << 2;
    float4 a = *reinterpret_cast<const float4*>(g_p0 + c);
    float4 b = *reinterpret_cast<const float4*>(g_p1 + c);
    __half2* pm = reinterpret_cast<__half2*>(mh + c);
    pm[0] = __half2(__float2half_rn(a.x + b.x), __float2half_rn(a.y + b.y));
    pm[1] = __half2(__float2half_rn(a.z + b.z), __float2half_rn(a.w + b.w));
}

// ---------------------------------------------------------------------------
// HMMA GEMM, templated:
//   F16=false: bf16 split-3 sections (AhBh, AhBl, AlBh) — fp32 emulation
//   F16=true : fp16 2 sections (AhB, AlB) with single fp16 B
// CTA tile 128x128 (MI=4), 8 warps of 64x32, KC=64, cp.async 3-stage.
// Split-K via blockIdx.z (window z*K..(z+1)*K, output Cf / Cf1).
// ---------------------------------------------------------------------------
constexpr int BN = 128, KC = 64;
constexpr int NSTAGE = 3;
constexpr int APITCH = 144;                 // 128B data + 16B pad
constexpr int BPITCH = 272;                 // 256B data + 16B pad
constexpr int B_BYTES = KC * BPITCH;        // 17408
constexpr int MI = 4;                       // BM = 128
constexpr int A_BYTES = MI * 32 * APITCH;   // 18432
constexpr int STAGE_BYTES = A_BYTES + B_BYTES;
constexpr int SMEMT = NSTAGE * STAGE_BYTES; // 107520 -> 2 CTA/SM

__device__ __forceinline__ void issue_chunk(
    uint32_t sbase, int st,
    const uint16_t* Aptr, const uint16_t* Bptr,
    int lda, int ldb, int m0, int n0, int k0, int tid)
{
    const uint32_t sA = sbase + st * STAGE_BYTES;
    const uint32_t sB = sA + A_BYTES;
    const int arow = tid >> 3, ack = tid & 7;
    const int brow = tid >> 4, bck = tid & 15;
    #pragma unroll
    for (int p = 0; p < 4; p++) {
        const int r = arow + p * 32;
        cp16(sA + r * APITCH + ack * 16,
             Aptr + (size_t)(m0 + r) * lda + k0 + ack * 8);
        const int kr = brow + p * 16;
        cp16(sB + kr * BPITCH + bck * 16,
             Bptr + (size_t)(k0 + kr) * ldb + n0 + bck * 8);
    }
    CP_COMMIT();
}

template<bool F16>
__global__ __launch_bounds__(256, 2)
void gemm_split(const uint16_t* __restrict__ Ah, const uint16_t* __restrict__ Al, int lda,
                const uint16_t* __restrict__ Bh, const uint16_t* __restrict__ Bl, int ldb,
                float* __restrict__ Cf, float* __restrict__ Cf1,
                const float* __restrict__ bias,
                int ldc, int K)
{
    extern __shared__ char smem[];
    const uint32_t sbase = smem_u32(smem);
    const int tid  = threadIdx.x;
    const int wid  = tid >> 5;
    const int lane = tid & 31;
    const int wr   = wid >> 2;     // 0..1  (warp row: 64 rows each)
    const int wc   = wid & 3;      // 0..3  (warp col: 32 cols each)
    const int m0   = blockIdx.y * 128;
    const int n0   = blockIdx.x * BN;
    const int z    = blockIdx.z;   // split-K index

    Ah += (size_t)z * K;
    Al += (size_t)z * K;
    Bh += (size_t)z * K * ldb;
    if (!F16) Bl += (size_t)z * K * ldb;
    float* Csel = (z == 0) ? Cf : Cf1;

    const int NSECT = F16 ? 2 : 3;
    const int NSEC  = K / KC;
    const int NCH   = NSECT * NSEC;

    auto chunk_src = [&](int ch, const uint16_t*& Ap, const uint16_t*& Bp, int& k0) {
        const int sec = ch / NSEC;
        const int kk  = ch - sec * NSEC;
        if (F16) {
            Ap = (sec == 0) ? Ah : Al;
            Bp = Bh;
        } else {
            Ap = (sec < 2) ? Ah : Al;
            Bp = (sec == 1) ? Bl : Bh;
        }
        k0 = kk * KC;
    };

    float d[4][4][4];
    #pragma unroll
    for (int mi = 0; mi < 4; mi++)
        #pragma unroll
        for (int ni = 0; ni < 4; ni++)
            #pragma unroll
            for (int r = 0; r < 4; r++) d[mi][ni][r] = 0.0f;

    // Prologue: stages 0, 1
    #pragma unroll
    for (int s = 0; s < NSTAGE - 1; s++) {
        const uint16_t *Ap, *Bp; int k0;
        chunk_src(s, Ap, Bp, k0);
        issue_chunk(sbase, s, Ap, Bp, lda, ldb, m0, n0, k0, tid);
    }

    for (int ch = 0; ch < NCH; ch++) {
        if (ch + 2 < NCH) {
            const uint16_t *Ap, *Bp; int k0;
            chunk_src(ch + 2, Ap, Bp, k0);
            issue_chunk(sbase, (ch + 2) % NSTAGE, Ap, Bp, lda, ldb, m0, n0, k0, tid);
        }
        if (ch + 2 < NCH)       asm volatile("cp.async.wait_group 2;" ::: "memory");
        else if (ch + 1 < NCH)  asm volatile("cp.async.wait_group 1;" ::: "memory");
        else                    asm volatile("cp.async.wait_group 0;" ::: "memory");
        __syncthreads();

        const uint32_t sA = sbase + (ch % NSTAGE) * STAGE_BYTES;
        const uint32_t sB = sA + A_BYTES;

        #pragma unroll
        for (int ki = 0; ki < KC / 16; ki++) {
            uint32_t a[4][4];
            #pragma unroll
            for (int mi = 0; mi < 4; mi++) {
                const uint32_t addr = sA
                    + (uint32_t)(wr * 64 + mi * 16 + (lane & 15)) * APITCH
                    + (uint32_t)((lane >> 4) * 8 + ki * 16) * 2;
                asm volatile("ldmatrix.sync.aligned.m8n8.x4.shared.b16 {%0,%1,%2,%3}, [%4];"
                    : "=r"(a[mi][0]), "=r"(a[mi][1]), "=r"(a[mi][2]), "=r"(a[mi][3])
                    : "r"(addr));
            }
            uint32_t b[4][2];
            #pragma unroll
            for (int t = 0; t < 2; t++) {
                const uint32_t addr = sB
                    + (uint32_t)(ki * 16 + (lane & 15)) * BPITCH
                    + (uint32_t)(wc * 32 + t * 16 + (lane >> 4) * 8) * 2;
                uint32_t r0, r1, r2, r3;
                asm volatile("ldmatrix.sync.aligned.m8n8.x4.trans.shared.b16 {%0,%1,%2,%3}, [%4];"
                    : "=r"(r0), "=r"(r1), "=r"(r2), "=r"(r3) : "r"(addr));
                b[2 * t][0] = r0;  b[2 * t][1] = r1;
                b[2 * t + 1][0] = r2;  b[2 * t + 1][1] = r3;
            }
            #pragma unroll
            for (int mi = 0; mi < 4; mi++)
                #pragma unroll
                for (int ni = 0; ni < 4; ni++)
                    mma16<F16>(d[mi][ni], a[mi], b[ni]);
        }
        __syncthreads();
    }

    // ---- Epilogue: fp32 output (+ optional bias) ----
    #pragma unroll
    for (int mi = 0; mi < 4; mi++) {
        const int mrow = m0 + wr * 64 + mi * 16 + (lane >> 2);
        #pragma unroll
        for (int ni = 0; ni < 4; ni++) {
            const int ncol = n0 + wc * 32 + ni * 8 + (lane & 3) * 2;
            #pragma unroll
            for (int half = 0; half < 2; half++) {
                const int r = mrow + half * 8;
                float v0 = d[mi][ni][half * 2 + 0];
                float v1 = d[mi][ni][half * 2 + 1];
                if (bias != nullptr) { v0 += bias[ncol]; v1 += bias[ncol + 1]; }
                float2 o; o.x = v0; o.y = v1;
                *reinterpret_cast<float2*>(Csel + (size_t)r * ldc + ncol) = o;
            }
        }
    }
}

// ---------------------------------------------------------------------------
// Fused bias, parallel: c[j] = sum_k b_v[k] * w_proj[k, j] + b_proj[j]
// ---------------------------------------------------------------------------
__global__ void bias_partial_kernel(const float* __restrict__ b_qkv,
                                    const float* __restrict__ w_proj)
{
    const int j  = blockIdx.x * blockDim.x + threadIdx.x;
    const int s  = blockIdx.y;
    const int kb = s * (DIM / KSLICES);
    float acc = 0.0f;
    #pragma unroll 8
    for (int k = 0; k < DIM / KSLICES; k++)
        acc += b_qkv[2 * DIM + kb + k] * w_proj[(size_t)(kb + k) * DIM + j];
    g_cpart[s * DIM + j] = acc;
}

__global__ void bias_reduce_kernel(const float* __restrict__ b_proj)
{
    const int j = blockIdx.x * blockDim.x + threadIdx.x;
    if (j >= DIM) return;
    float acc = b_proj[j];
    #pragma unroll
    for (int s = 0; s < KSLICES; s++) acc += g_cpart[s * DIM + j];
    g_c[j] = acc;
}

// ---------------------------------------------------------------------------
// kernel_launch  (serial, single default stream)
// Math: softmax rows sum to 1 and the reference's final einsum contracts k
// over attn only, so out == v. Head permutations cancel on flattened layout:
//   out = x @ (w_qkv[:,2C:3C] @ w_proj) + (b_qkv[2C:3C] @ w_proj + b_proj)
// GEMM1 (M-build): bf16 split-3, split-K x2 -> fp32 partials -> fp16 M.
// GEMM2 (main):    fp16 2-term (xh + xl) @ Mh  — err ~2^-12 ≈ 1e-4 rel.
// ---------------------------------------------------------------------------
extern "C" void kernel_launch(void* const* d_in, const int* in_sizes, int n_in,
                              void* d_out, int out_size)
{
    const float* x      = (const float*)d_in[0];  // [4096, 1024]
    const float* w_qkv  = (const float*)d_in[1];  // [1024, 3072]
    const float* b_qkv  = (const float*)d_in[2];  // [3072]
    const float* w_proj = (const float*)d_in[3];  // [1024, 1024]
    const float* b_proj = (const float*)d_in[4];  // [1024]
    float* out = (float*)d_out;                   // [4096, 1024]

    __half *xh, *xl, *mh;
    __nv_bfloat16 *wvh, *wvl, *wph, *wpl;
    float *pc, *p0, *p1;
    cudaGetSymbolAddress((void**)&xh,  g_xh);
    cudaGetSymbolAddress((void**)&xl,  g_xl);
    cudaGetSymbolAddress((void**)&wvh, g_wvh);
    cudaGetSymbolAddress((void**)&wvl, g_wvl);
    cudaGetSymbolAddress((void**)&wph, g_wph);
    cudaGetSymbolAddress((void**)&wpl, g_wpl);
    cudaGetSymbolAddress((void**)&mh,  g_mh);
    cudaGetSymbolAddress((void**)&pc,  g_c);
    cudaGetSymbolAddress((void**)&p0,  g_p0);
    cudaGetSymbolAddress((void**)&p1,  g_p1);

    cudaFuncSetAttribute(gemm_split<false>, cudaFuncAttributeMaxDynamicSharedMemorySize, SMEMT);
    cudaFuncSetAttribute(gemm_split<true>,  cudaFuncAttributeMaxDynamicSharedMemorySize, SMEMT);

    // 1) Split conversions
    split_bf16_kernel<<<(DIM * DIM / 4 + 255) / 256, 256>>>(w_qkv + 2 * DIM, 3 * DIM, wvh, wvl, DIM, DIM);
    split_bf16_kernel<<<(DIM * DIM / 4 + 255) / 256, 256>>>(w_proj, DIM, wph, wpl, DIM, DIM);
    split_f16_kernel<<<(ROWS * DIM / 4 + 255) / 256, 256>>>(x, xh, xl, ROWS * DIM / 4);

    // 2) fused bias (parallel two-phase, no atomics)
    {
        dim3 grid(DIM / 256, KSLICES);
        bias_partial_kernel<<<grid, 256>>>(b_qkv, w_proj);
        bias_reduce_kernel<<<DIM / 256, 256>>>(b_proj);
    }

    // 3) GEMM1: M = Wv @ Wp, bf16 split-3, split-K x2 (128 CTAs) -> fp32 partials
    {
        dim3 grid(DIM / BN, DIM / 128, 2);   // 8 x 8 x 2
        gemm_split<false><<<grid, 256, SMEMT>>>(
            (const uint16_t*)wvh, (const uint16_t*)wvl, DIM,
            (const uint16_t*)wph, (const uint16_t*)wpl, DIM,
            p0, p1, nullptr, DIM, DIM / 2);
    }
    // 3b) combine partials -> single fp16 M
    combine_f16_kernel<<<(DIM * DIM / 4 + 255) / 256, 256>>>(mh);

    // 4) GEMM2: out = (xh + xl) @ Mh + c   (fp16 2-term, 32 chunks)
    {
        dim3 grid(DIM / BN, ROWS / 128, 1);  // 8 x 32
        gemm_split<true><<<grid, 256, SMEMT>>>(
            (const uint16_t*)xh, (const uint16_t*)xl, DIM,
            (const uint16_t*)mh, nullptr, DIM,
            out, nullptr, pc, DIM, DIM);
    }
}

// round 11
// speedup vs baseline: 1.8059x; 1.4154x over previous
#include <cuda_runtime.h>
#include <cuda_bf16.h>
#include <cuda_fp16.h>
#include <cstdint>

// ---------------------------------------------------------------------------
// Problem constants
// ---------------------------------------------------------------------------
constexpr int DIM  = 1024;
constexpr int ROWS = 4096;   // BATCH * SEQ

// ---------------------------------------------------------------------------
// Device scratch (allocation-free per harness rules)
// x rounded to fp16 (single term; adds ~2^-12 RMS rel error).
// weights split into bf16 (hi, lo) for the 3-term weight-fusion GEMM.
// M stored as a single fp16 buffer (error 2^-12; dominates with x's term).
// ---------------------------------------------------------------------------
__device__ __align__(16) __half        g_xh[ROWS * DIM];
__device__ __align__(16) __nv_bfloat16 g_wvh[DIM * DIM];
__device__ __align__(16) __nv_bfloat16 g_wvl[DIM * DIM];
__device__ __align__(16) __nv_bfloat16 g_wph[DIM * DIM];
__device__ __align__(16) __nv_bfloat16 g_wpl[DIM * DIM];
__device__ __align__(16) __half        g_mh[DIM * DIM];   // M = Wv @ Wp (fp16)
__device__ __align__(16) float g_p0[DIM * DIM];           // split-K partial 0
__device__ __align__(16) float g_p1[DIM * DIM];           // split-K partial 1
__device__ float g_c[DIM];                                 // fused bias
constexpr int KSLICES = 16;
__device__ float g_cpart[KSLICES * DIM];                   // bias partials

// ---------------------------------------------------------------------------
// Helpers
// ---------------------------------------------------------------------------
__device__ __forceinline__ uint32_t smem_u32(const void* p) {
    uint32_t a;
    asm("{ .reg .u64 t; cvta.to.shared.u64 t, %1; cvt.u32.u64 %0, t; }" : "=r"(a) : "l"(p));
    return a;
}
__device__ __forceinline__ void cp16(uint32_t dst, const void* src) {
    asm volatile("cp.async.cg.shared.global [%0], [%1], 16;" :: "r"(dst), "l"(src));
}
#define CP_COMMIT() asm volatile("cp.async.commit_group;" ::: "memory")

template<bool F16>
__device__ __forceinline__ void mma16(float d[4], const uint32_t a[4], const uint32_t b[2]) {
    if (F16) {
        asm volatile(
            "mma.sync.aligned.m16n8k16.row.col.f32.f16.f16.f32 "
            "{%0,%1,%2,%3}, {%4,%5,%6,%7}, {%8,%9}, {%0,%1,%2,%3};"
            : "+f"(d[0]), "+f"(d[1]), "+f"(d[2]), "+f"(d[3])
            : "r"(a[0]), "r"(a[1]), "r"(a[2]), "r"(a[3]), "r"(b[0]), "r"(b[1]));
    } else {
        asm volatile(
            "mma.sync.aligned.m16n8k16.row.col.f32.bf16.bf16.f32 "
            "{%0,%1,%2,%3}, {%4,%5,%6,%7}, {%8,%9}, {%0,%1,%2,%3};"
            : "+f"(d[0]), "+f"(d[1]), "+f"(d[2]), "+f"(d[3])
            : "r"(a[0]), "r"(a[1]), "r"(a[2]), "r"(a[3]), "r"(b[0]), "r"(b[1]));
    }
}

// ---------------------------------------------------------------------------
// Conversion kernels
// ---------------------------------------------------------------------------
__global__ void split_bf16_kernel(const float* __restrict__ in, int ld,
                                  __nv_bfloat16* __restrict__ hi,
                                  __nv_bfloat16* __restrict__ lo,
                                  int rows, int cols)
{
    const int idx = blockIdx.x * blockDim.x + threadIdx.x;
    const int c4 = cols >> 2;
    if (idx >= rows * c4) return;
    const int r = idx / c4;
    const int c = (idx - r * c4) << 2;
    float4 v = *reinterpret_cast<const float4*>(in + (size_t)r * ld + c);
    __nv_bfloat16 hx = __float2bfloat16(v.x), hy = __float2bfloat16(v.y);
    __nv_bfloat16 hz = __float2bfloat16(v.z), hw = __float2bfloat16(v.w);
    __nv_bfloat16 lx = __float2bfloat16(v.x - __bfloat162float(hx));
    __nv_bfloat16 ly = __float2bfloat16(v.y - __bfloat162float(hy));
    __nv_bfloat16 lz = __float2bfloat16(v.z - __bfloat162float(hz));
    __nv_bfloat16 lw = __float2bfloat16(v.w - __bfloat162float(hw));
    __nv_bfloat162* ph = reinterpret_cast<__nv_bfloat162*>(hi + (size_t)r * cols + c);
    ph[0] = __nv_bfloat162(hx, hy);  ph[1] = __nv_bfloat162(hz, hw);
    __nv_bfloat162* pl = reinterpret_cast<__nv_bfloat162*>(lo + (size_t)r * cols + c);
    pl[0] = __nv_bfloat162(lx, ly);  pl[1] = __nv_bfloat162(lz, lw);
}

// Straight fp32 -> fp16 convert (single term)
__global__ void cvt_f16_kernel(const float* __restrict__ in,
                               __half* __restrict__ out16, int n4)
{
    const int idx = blockIdx.x * blockDim.x + threadIdx.x;
    if (idx >= n4) return;
    const int c = idx << 2;
    float4 v = *reinterpret_cast<const float4*>(in + c);
    __half2* po = reinterpret_cast<__half2*>(out16 + c);
    po[0] = __half2(__float2half_rn(v.x), __float2half_rn(v.y));
    po[1] = __half2(__float2half_rn(v.z), __float2half_rn(v.w));
}

// Combine split-K partials -> single fp16 M
__global__ void combine_f16_kernel(__half* __restrict__ mh)
{
    const int idx = blockIdx.x * blockDim.x + threadIdx.x;
    if (idx >= DIM * DIM / 4) return;
    const int c = idx << 2;
    float4 a = *reinterpret_cast<const float4*>(g_p0 + c);
    float4 b = *reinterpret_cast<const float4*>(g_p1 + c);
    __half2* pm = reinterpret_cast<__half2*>(mh + c);
    pm[0] = __half2(__float2half_rn(a.x + b.x), __float2half_rn(a.y + b.y));
    pm[1] = __half2(__float2half_rn(a.z + b.z), __float2half_rn(a.w + b.w));
}

// ---------------------------------------------------------------------------
// HMMA GEMM, templated:
//   F16=true,  NSECT=1: plain fp16 GEMM (A @ B)
//   F16=false, NSECT=3: bf16 split-3 (AhBh + AhBl + AlBh) fp32 emulation
// CTA tile 128x128, 8 warps of 64x32, KC=64, cp.async 3-stage, 2 CTA/SM.
// Split-K via blockIdx.z (window z*K..(z+1)*K, output Cf / Cf1).
// ---------------------------------------------------------------------------
constexpr int BN = 128, KC = 64;
constexpr int NSTAGE = 3;
constexpr int APITCH = 144;                 // 128B data + 16B pad
constexpr int BPITCH = 272;                 // 256B data + 16B pad
constexpr int B_BYTES = KC * BPITCH;        // 17408
constexpr int A_BYTES = 128 * APITCH;       // 18432
constexpr int STAGE_BYTES = A_BYTES + B_BYTES;
constexpr int SMEMT = NSTAGE * STAGE_BYTES; // 107520 -> 2 CTA/SM

__device__ __forceinline__ void issue_chunk(
    uint32_t sbase, int st,
    const uint16_t* Aptr, const uint16_t* Bptr,
    int lda, int ldb, int m0, int n0, int k0, int tid)
{
    const uint32_t sA = sbase + st * STAGE_BYTES;
    const uint32_t sB = sA + A_BYTES;
    const int arow = tid >> 3, ack = tid & 7;
    const int brow = tid >> 4, bck = tid & 15;
    #pragma unroll
    for (int p = 0; p < 4; p++) {
        const int r = arow + p * 32;
        cp16(sA + r * APITCH + ack * 16,
             Aptr + (size_t)(m0 + r) * lda + k0 + ack * 8);
        const int kr = brow + p * 16;
        cp16(sB + kr * BPITCH + bck * 16,
             Bptr + (size_t)(k0 + kr) * ldb + n0 + bck * 8);
    }
    CP_COMMIT();
}

template<bool F16, int NSECT>
__global__ __launch_bounds__(256, 2)
void gemm_split(const uint16_t* __restrict__ Ah, const uint16_t* __restrict__ Al, int lda,
                const uint16_t* __restrict__ Bh, const uint16_t* __restrict__ Bl, int ldb,
                float* __restrict__ Cf, float* __restrict__ Cf1,
                const float* __restrict__ bias,
                int ldc, int K)
{
    extern __shared__ char smem[];
    const uint32_t sbase = smem_u32(smem);
    const int tid  = threadIdx.x;
    const int wid  = tid >> 5;
    const int lane = tid & 31;
    const int wr   = wid >> 2;     // 0..1  (warp row: 64 rows each)
    const int wc   = wid & 3;      // 0..3  (warp col: 32 cols each)
    const int m0   = blockIdx.y * 128;
    const int n0   = blockIdx.x * BN;
    const int z    = blockIdx.z;   // split-K index

    Ah += (size_t)z * K;
    if (NSECT > 1) Al += (size_t)z * K;
    Bh += (size_t)z * K * ldb;
    if (NSECT > 2) Bl += (size_t)z * K * ldb;
    float* Csel = (z == 0) ? Cf : Cf1;

    const int NSEC = K / KC;
    const int NCH  = NSECT * NSEC;

    auto chunk_src = [&](int ch, const uint16_t*& Ap, const uint16_t*& Bp, int& k0) {
        if (NSECT == 1) {
            Ap = Ah;  Bp = Bh;  k0 = ch * KC;
        } else {
            const int sec = ch / NSEC;
            const int kk  = ch - sec * NSEC;
            Ap = (sec < 2) ? Ah : Al;
            Bp = (sec == 1) ? Bl : Bh;
            k0 = kk * KC;
        }
    };

    float d[4][4][4];
    #pragma unroll
    for (int mi = 0; mi < 4; mi++)
        #pragma unroll
        for (int ni = 0; ni < 4; ni++)
            #pragma unroll
            for (int r = 0; r < 4; r++) d[mi][ni][r] = 0.0f;

    // Prologue: stages 0, 1
    #pragma unroll
    for (int s = 0; s < NSTAGE - 1; s++) {
        const uint16_t *Ap, *Bp; int k0;
        chunk_src(s, Ap, Bp, k0);
        issue_chunk(sbase, s, Ap, Bp, lda, ldb, m0, n0, k0, tid);
    }

    for (int ch = 0; ch < NCH; ch++) {
        if (ch + 2 < NCH) {
            const uint16_t *Ap, *Bp; int k0;
            chunk_src(ch + 2, Ap, Bp, k0);
            issue_chunk(sbase, (ch + 2) % NSTAGE, Ap, Bp, lda, ldb, m0, n0, k0, tid);
        }
        if (ch + 2 < NCH)       asm volatile("cp.async.wait_group 2;" ::: "memory");
        else if (ch + 1 < NCH)  asm volatile("cp.async.wait_group 1;" ::: "memory");
        else                    asm volatile("cp.async.wait_group 0;" ::: "memory");
        __syncthreads();

        const uint32_t sA = sbase + (ch % NSTAGE) * STAGE_BYTES;
        const uint32_t sB = sA + A_BYTES;

        #pragma unroll
        for (int ki = 0; ki < KC / 16; ki++) {
            uint32_t a[4][4];
            #pragma unroll
            for (int mi = 0; mi < 4; mi++) {
                const uint32_t addr = sA
                    + (uint32_t)(wr * 64 + mi * 16 + (lane & 15)) * APITCH
                    + (uint32_t)((lane >> 4) * 8 + ki * 16) * 2;
                asm volatile("ldmatrix.sync.aligned.m8n8.x4.shared.b16 {%0,%1,%2,%3}, [%4];"
                    : "=r"(a[mi][0]), "=r"(a[mi][1]), "=r"(a[mi][2]), "=r"(a[mi][3])
                    : "r"(addr));
            }
            uint32_t b[4][2];
            #pragma unroll
            for (int t = 0; t < 2; t++) {
                const uint32_t addr = sB
                    + (uint32_t)(ki * 16 + (lane & 15)) * BPITCH
                    + (uint32_t)(wc * 32 + t * 16 + (lane >> 4) * 8) * 2;
                uint32_t r0, r1, r2, r3;
                asm volatile("ldmatrix.sync.aligned.m8n8.x4.trans.shared.b16 {%0,%1,%2,%3}, [%4];"
                    : "=r"(r0), "=r"(r1), "=r"(r2), "=r"(r3) : "r"(addr));
                b[2 * t][0] = r0;  b[2 * t][1] = r1;
                b[2 * t + 1][0] = r2;  b[2 * t + 1][1] = r3;
            }
            #pragma unroll
            for (int mi = 0; mi < 4; mi++)
                #pragma unroll
                for (int ni = 0; ni < 4; ni++)
                    mma16<F16>(d[mi][ni], a[mi], b[ni]);
        }
        __syncthreads();
    }

    // ---- Epilogue: fp32 output (+ optional bias) ----
    #pragma unroll
    for (int mi = 0; mi < 4; mi++) {
        const int mrow = m0 + wr * 64 + mi * 16 + (lane >> 2);
        #pragma unroll
        for (int ni = 0; ni < 4; ni++) {
            const int ncol = n0 + wc * 32 + ni * 8 + (lane & 3) * 2;
            #pragma unroll
            for (int half = 0; half < 2; half++) {
                const int r = mrow + half * 8;
                float v0 = d[mi][ni][half * 2 + 0];
                float v1 = d[mi][ni][half * 2 + 1];
                if (bias != nullptr) { v0 += bias[ncol]; v1 += bias[ncol + 1]; }
                float2 o; o.x = v0; o.y = v1;
                *reinterpret_cast<float2*>(Csel + (size_t)r * ldc + ncol) = o;
            }
        }
    }
}

// ---------------------------------------------------------------------------
// Fused bias, parallel: c[j] = sum_k b_v[k] * w_proj[k, j] + b_proj[j]
// ---------------------------------------------------------------------------
__global__ void bias_partial_kernel(const float* __restrict__ b_qkv,
                                    const float* __restrict__ w_proj)
{
    const int j  = blockIdx.x * blockDim.x + threadIdx.x;
    const int s  = blockIdx.y;
    const int kb = s * (DIM / KSLICES);
    float acc = 0.0f;
    #pragma unroll 8
    for (int k = 0; k < DIM / KSLICES; k++)
        acc += b_qkv[2 * DIM + kb + k] * w_proj[(size_t)(kb + k) * DIM + j];
    g_cpart[s * DIM + j] = acc;
}

__global__ void bias_reduce_kernel(const float* __restrict__ b_proj)
{
    const int j = blockIdx.x * blockDim.x + threadIdx.x;
    if (j >= DIM) return;
    float acc = b_proj[j];
    #pragma unroll
    for (int s = 0; s < KSLICES; s++) acc += g_cpart[s * DIM + j];
    g_c[j] = acc;
}

// ---------------------------------------------------------------------------
// kernel_launch  (serial, single default stream)
// Math: softmax rows sum to 1 and the reference's final einsum contracts k
// over attn only, so out == v. Head permutations cancel on flattened layout:
//   out = x @ (w_qkv[:,2C:3C] @ w_proj) + (b_qkv[2C:3C] @ w_proj + b_proj)
// GEMM1 (M-build): bf16 split-3, split-K x2 -> fp32 partials -> fp16 M.
// GEMM2 (main):    plain fp16  x16 @ M16  — err ~sqrt(2)*2^-12 ≈ 3e-4 rel.
// ---------------------------------------------------------------------------
extern "C" void kernel_launch(void* const* d_in, const int* in_sizes, int n_in,
                              void* d_out, int out_size)
{
    const float* x      = (const float*)d_in[0];  // [4096, 1024]
    const float* w_qkv  = (const float*)d_in[1];  // [1024, 3072]
    const float* b_qkv  = (const float*)d_in[2];  // [3072]
    const float* w_proj = (const float*)d_in[3];  // [1024, 1024]
    const float* b_proj = (const float*)d_in[4];  // [1024]
    float* out = (float*)d_out;                   // [4096, 1024]

    __half *xh, *mh;
    __nv_bfloat16 *wvh, *wvl, *wph, *wpl;
    float *pc, *p0, *p1;
    cudaGetSymbolAddress((void**)&xh,  g_xh);
    cudaGetSymbolAddress((void**)&wvh, g_wvh);
    cudaGetSymbolAddress((void**)&wvl, g_wvl);
    cudaGetSymbolAddress((void**)&wph, g_wph);
    cudaGetSymbolAddress((void**)&wpl, g_wpl);
    cudaGetSymbolAddress((void**)&mh,  g_mh);
    cudaGetSymbolAddress((void**)&pc,  g_c);
    cudaGetSymbolAddress((void**)&p0,  g_p0);
    cudaGetSymbolAddress((void**)&p1,  g_p1);

    cudaFuncSetAttribute((const void*)gemm_split<false,3>, cudaFuncAttributeMaxDynamicSharedMemorySize, SMEMT);
    cudaFuncSetAttribute((const void*)gemm_split<true,1>,  cudaFuncAttributeMaxDynamicSharedMemorySize, SMEMT);

    // 1) Conversions
    split_bf16_kernel<<<(DIM * DIM / 4 + 255) / 256, 256>>>(w_qkv + 2 * DIM, 3 * DIM, wvh, wvl, DIM, DIM);
    split_bf16_kernel<<<(DIM * DIM / 4 + 255) / 256, 256>>>(w_proj, DIM, wph, wpl, DIM, DIM);
    cvt_f16_kernel<<<(ROWS * DIM / 4 + 255) / 256, 256>>>(x, xh, ROWS * DIM / 4);

    // 2) fused bias (parallel two-phase, no atomics)
    {
        dim3 grid(DIM / 256, KSLICES);
        bias_partial_kernel<<<grid, 256>>>(b_qkv, w_proj);
        bias_reduce_kernel<<<DIM / 256, 256>>>(b_proj);
    }

    // 3) GEMM1: M = Wv @ Wp, bf16 split-3, split-K x2 (128 CTAs) -> fp32 partials
    {
        dim3 grid(DIM / BN, DIM / 128, 2);   // 8 x 8 x 2
        gemm_split<false,3><<<grid, 256, SMEMT>>>(
            (const uint16_t*)wvh, (const uint16_t*)wvl, DIM,
            (const uint16_t*)wph, (const uint16_t*)wpl, DIM,
            p0, p1, nullptr, DIM, DIM / 2);
    }
    // 3b) combine partials -> single fp16 M
    combine_f16_kernel<<<(DIM * DIM / 4 + 255) / 256, 256>>>(mh);

    // 4) GEMM2: out = x16 @ M16 + c   (plain fp16, 16 chunks)
    {
        dim3 grid(DIM / BN, ROWS / 128, 1);  // 8 x 32
        gemm_split<true,1><<<grid, 256, SMEMT>>>(
            (const uint16_t*)xh, nullptr, DIM,
            (const uint16_t*)mh, nullptr, DIM,
            out, nullptr, pc, DIM, DIM);
    }
}

// round 12
// speedup vs baseline: 2.2941x; 1.2703x over previous
#include <cuda_runtime.h>
#include <cuda_fp16.h>
#include <cstdint>

// ---------------------------------------------------------------------------
// Problem constants
// ---------------------------------------------------------------------------
constexpr int DIM  = 1024;
constexpr int ROWS = 4096;   // BATCH * SEQ

// ---------------------------------------------------------------------------
// Device scratch (allocation-free per harness rules)
// All GEMM operands rounded to fp16. Four independent rounding sources
// (Wv, Wp, M, x), each ~2.08e-4 empirical rel_err, quadrature ~4.2e-4.
// ---------------------------------------------------------------------------
__device__ __align__(16) __half g_xh[ROWS * DIM];
__device__ __align__(16) __half g_wv[DIM * DIM];
__device__ __align__(16) __half g_wp[DIM * DIM];
__device__ __align__(16) __half g_mh[DIM * DIM];   // M = Wv @ Wp (fp16)
__device__ __align__(16) float g_p0[DIM * DIM];    // split-K partial 0
__device__ __align__(16) float g_p1[DIM * DIM];    // split-K partial 1
__device__ float g_c[DIM];                          // fused bias
constexpr int KSLICES = 64;
__device__ float g_cpart[KSLICES * DIM];            // bias partials

// ---------------------------------------------------------------------------
// Helpers
// ---------------------------------------------------------------------------
__device__ __forceinline__ uint32_t smem_u32(const void* p) {
    uint32_t a;
    asm("{ .reg .u64 t; cvta.to.shared.u64 t, %1; cvt.u32.u64 %0, t; }" : "=r"(a) : "l"(p));
    return a;
}
__device__ __forceinline__ void cp16(uint32_t dst, const void* src) {
    asm volatile("cp.async.cg.shared.global [%0], [%1], 16;" :: "r"(dst), "l"(src));
}
#define CP_COMMIT() asm volatile("cp.async.commit_group;" ::: "memory")

__device__ __forceinline__ void mma_f16(float d[4], const uint32_t a[4], const uint32_t b[2]) {
    asm volatile(
        "mma.sync.aligned.m16n8k16.row.col.f32.f16.f16.f32 "
        "{%0,%1,%2,%3}, {%4,%5,%6,%7}, {%8,%9}, {%0,%1,%2,%3};"
        : "+f"(d[0]), "+f"(d[1]), "+f"(d[2]), "+f"(d[3])
        : "r"(a[0]), "r"(a[1]), "r"(a[2]), "r"(a[3]), "r"(b[0]), "r"(b[1]));
}

// ---------------------------------------------------------------------------
// Conversion kernels: fp32 (leading dim ld) -> fp16 dense
// ---------------------------------------------------------------------------
__global__ void cvt_f16_kernel(const float* __restrict__ in, int ld,
                               __half* __restrict__ out16,
                               int rows, int cols)
{
    const int idx = blockIdx.x * blockDim.x + threadIdx.x;
    const int c4 = cols >> 2;
    if (idx >= rows * c4) return;
    const int r = idx / c4;
    const int c = (idx - r * c4) << 2;
    float4 v = *reinterpret_cast<const float4*>(in + (size_t)r * ld + c);
    __half2* po = reinterpret_cast<__half2*>(out16 + (size_t)r * cols + c);
    po[0] = __half2(__float2half_rn(v.x), __float2half_rn(v.y));
    po[1] = __half2(__float2half_rn(v.z), __float2half_rn(v.w));
}

// Combine split-K partials -> single fp16 M
__global__ void combine_f16_kernel(__half* __restrict__ mh)
{
    const int idx = blockIdx.x * blockDim.x + threadIdx.x;
    if (idx >= DIM * DIM / 4) return;
    const int c = idx << 2;
    float4 a = *reinterpret_cast<const float4*>(g_p0 + c);
    float4 b = *reinterpret_cast<const float4*>(g_p1 + c);
    __half2* pm = reinterpret_cast<__half2*>(mh + c);
    pm[0] = __half2(__float2half_rn(a.x + b.x), __float2half_rn(a.y + b.y));
    pm[1] = __half2(__float2half_rn(a.z + b.z), __float2half_rn(a.w + b.w));
}

// ---------------------------------------------------------------------------
// Plain fp16 HMMA GEMM:  C[M,N] = A[M,K] @ B[K,N] (+ bias)
// CTA tile 128x128, 8 warps of 64x32, KC=64, cp.async 3-stage, 2 CTA/SM.
// Split-K via blockIdx.z (window z*K..(z+1)*K, output Cf / Cf1, fp32).
// ---------------------------------------------------------------------------
constexpr int BN = 128, KC = 64;
constexpr int NSTAGE = 3;
constexpr int APITCH = 144;                 // 128B data + 16B pad
constexpr int BPITCH = 272;                 // 256B data + 16B pad
constexpr int B_BYTES = KC * BPITCH;        // 17408
constexpr int A_BYTES = 128 * APITCH;       // 18432
constexpr int STAGE_BYTES = A_BYTES + B_BYTES;
constexpr int SMEMT = NSTAGE * STAGE_BYTES; // 107520 -> 2 CTA/SM

__device__ __forceinline__ void issue_chunk(
    uint32_t sbase, int st,
    const __half* Aptr, const __half* Bptr,
    int lda, int ldb, int m0, int n0, int k0, int tid)
{
    const uint32_t sA = sbase + st * STAGE_BYTES;
    const uint32_t sB = sA + A_BYTES;
    const int arow = tid >> 3, ack = tid & 7;
    const int brow = tid >> 4, bck = tid & 15;
    #pragma unroll
    for (int p = 0; p < 4; p++) {
        const int r = arow + p * 32;
        cp16(sA + r * APITCH + ack * 16,
             Aptr + (size_t)(m0 + r) * lda + k0 + ack * 8);
        const int kr = brow + p * 16;
        cp16(sB + kr * BPITCH + bck * 16,
             Bptr + (size_t)(k0 + kr) * ldb + n0 + bck * 8);
    }
    CP_COMMIT();
}

__global__ __launch_bounds__(256, 2)
void gemm_f16(const __half* __restrict__ A, int lda,
              const __half* __restrict__ B, int ldb,
              float* __restrict__ Cf, float* __restrict__ Cf1,
              const float* __restrict__ bias,
              int ldc, int K)
{
    extern __shared__ char smem[];
    const uint32_t sbase = smem_u32(smem);
    const int tid  = threadIdx.x;
    const int wid  = tid >> 5;
    const int lane = tid & 31;
    const int wr   = wid >> 2;     // 0..1  (warp row: 64 rows each)
    const int wc   = wid & 3;      // 0..3  (warp col: 32 cols each)
    const int m0   = blockIdx.y * 128;
    const int n0   = blockIdx.x * BN;
    const int z    = blockIdx.z;   // split-K index

    A += (size_t)z * K;            // shift K window (columns of A)
    B += (size_t)z * K * ldb;      // shift K window (rows of B)
    float* Csel = (z == 0) ? Cf : Cf1;

    const int NCH = K / KC;

    float d[4][4][4];
    #pragma unroll
    for (int mi = 0; mi < 4; mi++)
        #pragma unroll
        for (int ni = 0; ni < 4; ni++)
            #pragma unroll
            for (int r = 0; r < 4; r++) d[mi][ni][r] = 0.0f;

    // Prologue: stages 0, 1
    #pragma unroll
    for (int s = 0; s < NSTAGE - 1; s++)
        issue_chunk(sbase, s, A, B, lda, ldb, m0, n0, s * KC, tid);

    for (int ch = 0; ch < NCH; ch++) {
        if (ch + 2 < NCH)
            issue_chunk(sbase, (ch + 2) % NSTAGE, A, B, lda, ldb, m0, n0, (ch + 2) * KC, tid);
        if (ch + 2 < NCH)       asm volatile("cp.async.wait_group 2;" ::: "memory");
        else if (ch + 1 < NCH)  asm volatile("cp.async.wait_group 1;" ::: "memory");
        else                    asm volatile("cp.async.wait_group 0;" ::: "memory");
        __syncthreads();

        const uint32_t sA = sbase + (ch % NSTAGE) * STAGE_BYTES;
        const uint32_t sB = sA + A_BYTES;

        #pragma unroll
        for (int ki = 0; ki < KC / 16; ki++) {
            uint32_t a[4][4];
            #pragma unroll
            for (int mi = 0; mi < 4; mi++) {
                const uint32_t addr = sA
                    + (uint32_t)(wr * 64 + mi * 16 + (lane & 15)) * APITCH
                    + (uint32_t)((lane >> 4) * 8 + ki * 16) * 2;
                asm volatile("ldmatrix.sync.aligned.m8n8.x4.shared.b16 {%0,%1,%2,%3}, [%4];"
                    : "=r"(a[mi][0]), "=r"(a[mi][1]), "=r"(a[mi][2]), "=r"(a[mi][3])
                    : "r"(addr));
            }
            uint32_t b[4][2];
            #pragma unroll
            for (int t = 0; t < 2; t++) {
                const uint32_t addr = sB
                    + (uint32_t)(ki * 16 + (lane & 15)) * BPITCH
                    + (uint32_t)(wc * 32 + t * 16 + (lane >> 4) * 8) * 2;
                uint32_t r0, r1, r2, r3;
                asm volatile("ldmatrix.sync.aligned.m8n8.x4.trans.shared.b16 {%0,%1,%2,%3}, [%4];"
                    : "=r"(r0), "=r"(r1), "=r"(r2), "=r"(r3) : "r"(addr));
                b[2 * t][0] = r0;  b[2 * t][1] = r1;
                b[2 * t + 1][0] = r2;  b[2 * t + 1][1] = r3;
            }
            #pragma unroll
            for (int mi = 0; mi < 4; mi++)
                #pragma unroll
                for (int ni = 0; ni < 4; ni++)
                    mma_f16(d[mi][ni], a[mi], b[ni]);
        }
        __syncthreads();
    }

    // ---- Epilogue: fp32 output (+ optional bias) ----
    #pragma unroll
    for (int mi = 0; mi < 4; mi++) {
        const int mrow = m0 + wr * 64 + mi * 16 + (lane >> 2);
        #pragma unroll
        for (int ni = 0; ni < 4; ni++) {
            const int ncol = n0 + wc * 32 + ni * 8 + (lane & 3) * 2;
            #pragma unroll
            for (int half = 0; half < 2; half++) {
                const int r = mrow + half * 8;
                float v0 = d[mi][ni][half * 2 + 0];
                float v1 = d[mi][ni][half * 2 + 1];
                if (bias != nullptr) { v0 += bias[ncol]; v1 += bias[ncol + 1]; }
                float2 o; o.x = v0; o.y = v1;
                *reinterpret_cast<float2*>(Csel + (size_t)r * ldc + ncol) = o;
            }
        }
    }
}

// ---------------------------------------------------------------------------
// Fused bias, parallel: c[j] = sum_k b_v[k] * w_proj[k, j] + b_proj[j]
// KSLICES=64 -> 256 CTAs -> enough MLP to stream w_proj at full bandwidth.
// ---------------------------------------------------------------------------
__global__ void bias_partial_kernel(const float* __restrict__ b_qkv,
                                    const float* __restrict__ w_proj)
{
    const int j  = blockIdx.x * blockDim.x + threadIdx.x;
    const int s  = blockIdx.y;
    const int kb = s * (DIM / KSLICES);
    float acc = 0.0f;
    #pragma unroll
    for (int k = 0; k < DIM / KSLICES; k++)
        acc += b_qkv[2 * DIM + kb + k] * w_proj[(size_t)(kb + k) * DIM + j];
    g_cpart[s * DIM + j] = acc;
}

__global__ void bias_reduce_kernel(const float* __restrict__ b_proj)
{
    const int j = blockIdx.x * blockDim.x + threadIdx.x;
    if (j >= DIM) return;
    float acc = b_proj[j];
    #pragma unroll 16
    for (int s = 0; s < KSLICES; s++) acc += g_cpart[s * DIM + j];
    g_c[j] = acc;
}

// ---------------------------------------------------------------------------
// kernel_launch  (serial, single default stream)
// Math: softmax rows sum to 1 and the reference's final einsum contracts k
// over attn only, so out == v. Head permutations cancel on flattened layout:
//   out = x @ (w_qkv[:,2C:3C] @ w_proj) + (b_qkv[2C:3C] @ w_proj + b_proj)
// All GEMM operands fp16 (4 rounding sources, ~4.2e-4 total rel error).
// ---------------------------------------------------------------------------
extern "C" void kernel_launch(void* const* d_in, const int* in_sizes, int n_in,
                              void* d_out, int out_size)
{
    const float* x      = (const float*)d_in[0];  // [4096, 1024]
    const float* w_qkv  = (const float*)d_in[1];  // [1024, 3072]
    const float* b_qkv  = (const float*)d_in[2];  // [3072]
    const float* w_proj = (const float*)d_in[3];  // [1024, 1024]
    const float* b_proj = (const float*)d_in[4];  // [1024]
    float* out = (float*)d_out;                   // [4096, 1024]

    __half *xh, *wv, *wp, *mh;
    float *pc, *p0, *p1;
    cudaGetSymbolAddress((void**)&xh, g_xh);
    cudaGetSymbolAddress((void**)&wv, g_wv);
    cudaGetSymbolAddress((void**)&wp, g_wp);
    cudaGetSymbolAddress((void**)&mh, g_mh);
    cudaGetSymbolAddress((void**)&pc, g_c);
    cudaGetSymbolAddress((void**)&p0, g_p0);
    cudaGetSymbolAddress((void**)&p1, g_p1);

    cudaFuncSetAttribute(gemm_f16, cudaFuncAttributeMaxDynamicSharedMemorySize, SMEMT);

    // 1) Conversions to fp16
    cvt_f16_kernel<<<(DIM * DIM / 4 + 255) / 256, 256>>>(w_qkv + 2 * DIM, 3 * DIM, wv, DIM, DIM);
    cvt_f16_kernel<<<(DIM * DIM / 4 + 255) / 256, 256>>>(w_proj, DIM, wp, DIM, DIM);
    cvt_f16_kernel<<<(ROWS * DIM / 4 + 255) / 256, 256>>>(x, DIM, xh, ROWS, DIM);

    // 2) fused bias (parallel two-phase, no atomics)
    {
        dim3 grid(DIM / 256, KSLICES);
        bias_partial_kernel<<<grid, 256>>>(b_qkv, w_proj);
        bias_reduce_kernel<<<DIM / 256, 256>>>(b_proj);
    }

    // 3) GEMM1: M = Wv @ Wp, plain fp16, split-K x2 (128 CTAs) -> fp32 partials
    {
        dim3 grid(DIM / BN, DIM / 128, 2);   // 8 x 8 x 2
        gemm_f16<<<grid, 256, SMEMT>>>(wv, DIM, wp, DIM, p0, p1, nullptr, DIM, DIM / 2);
    }
    // 3b) combine partials -> single fp16 M
    combine_f16_kernel<<<(DIM * DIM / 4 + 255) / 256, 256>>>(mh);

    // 4) GEMM2: out = x16 @ M16 + c   (plain fp16, 16 chunks)
    {
        dim3 grid(DIM / BN, ROWS / 128, 1);  // 8 x 32
        gemm_f16<<<grid, 256, SMEMT>>>(xh, DIM, mh, DIM, out, nullptr, pc, DIM, DIM);
    }
}

// round 13
// speedup vs baseline: 2.5629x; 1.1172x over previous
#include <cuda_runtime.h>
#include <cuda_fp16.h>
#include <cstdint>

// ---------------------------------------------------------------------------
// Problem constants
// ---------------------------------------------------------------------------
constexpr int DIM  = 1024;
constexpr int ROWS = 4096;   // BATCH * SEQ

// ---------------------------------------------------------------------------
// Device scratch (allocation-free per harness rules)
// All GEMM operands rounded to fp16. Four independent rounding sources
// (Wv, Wp, M, x), each ~2.08e-4 empirical rel_err, quadrature ~4.2e-4.
// ---------------------------------------------------------------------------
__device__ __align__(16) __half g_xh[ROWS * DIM];
__device__ __align__(16) __half g_wv[DIM * DIM];
__device__ __align__(16) __half g_wp[DIM * DIM];
__device__ __align__(16) __half g_mh[DIM * DIM];   // M = Wv @ Wp (fp16)
__device__ __align__(16) float g_p0[DIM * DIM];    // split-K partial 0
__device__ __align__(16) float g_p1[DIM * DIM];    // split-K partial 1
__device__ float g_c[DIM];                          // fused bias
constexpr int KSLICES = 64;
__device__ float g_cpart[KSLICES * DIM];            // bias partials

// ---------------------------------------------------------------------------
// Helpers
// ---------------------------------------------------------------------------
__device__ __forceinline__ uint32_t smem_u32(const void* p) {
    uint32_t a;
    asm("{ .reg .u64 t; cvta.to.shared.u64 t, %1; cvt.u32.u64 %0, t; }" : "=r"(a) : "l"(p));
    return a;
}
__device__ __forceinline__ void cp16(uint32_t dst, const void* src) {
    asm volatile("cp.async.cg.shared.global [%0], [%1], 16;" :: "r"(dst), "l"(src));
}
#define CP_COMMIT() asm volatile("cp.async.commit_group;" ::: "memory")

__device__ __forceinline__ void mma_f16(float d[4], const uint32_t a[4], const uint32_t b[2]) {
    asm volatile(
        "mma.sync.aligned.m16n8k16.row.col.f32.f16.f16.f32 "
        "{%0,%1,%2,%3}, {%4,%5,%6,%7}, {%8,%9}, {%0,%1,%2,%3};"
        : "+f"(d[0]), "+f"(d[1]), "+f"(d[2]), "+f"(d[3])
        : "r"(a[0]), "r"(a[1]), "r"(a[2]), "r"(a[3]), "r"(b[0]), "r"(b[1]));
}

// ---------------------------------------------------------------------------
// Conversion kernels
// ---------------------------------------------------------------------------
__global__ void cvt_f16_kernel(const float* __restrict__ in, int ld,
                               __half* __restrict__ out16,
                               int rows, int cols)
{
    const int idx = blockIdx.x * blockDim.x + threadIdx.x;
    const int c4 = cols >> 2;
    if (idx >= rows * c4) return;
    const int r = idx / c4;
    const int c = (idx - r * c4) << 2;
    float4 v = *reinterpret_cast<const float4*>(in + (size_t)r * ld + c);
    __half2* po = reinterpret_cast<__half2*>(out16 + (size_t)r * cols + c);
    po[0] = __half2(__float2half_rn(v.x), __float2half_rn(v.y));
    po[1] = __half2(__float2half_rn(v.z), __float2half_rn(v.w));
}

// Both weight matrices in one launch: half the grid does Wv, half Wp.
__global__ void cvt_weights_kernel(const float* __restrict__ w_qkv,
                                   const float* __restrict__ w_proj,
                                   __half* __restrict__ wv,
                                   __half* __restrict__ wp)
{
    const int n4 = DIM * DIM / 4;
    int idx = blockIdx.x * blockDim.x + threadIdx.x;
    const float* in;  int ld;  __half* out16;
    if (idx < n4) {
        in = w_qkv + 2 * DIM;  ld = 3 * DIM;  out16 = wv;
    } else {
        idx -= n4;
        if (idx >= n4) return;
        in = w_proj;  ld = DIM;  out16 = wp;
    }
    const int c4 = DIM >> 2;
    const int r = idx / c4;
    const int c = (idx - r * c4) << 2;
    float4 v = *reinterpret_cast<const float4*>(in + (size_t)r * ld + c);
    __half2* po = reinterpret_cast<__half2*>(out16 + (size_t)r * DIM + c);
    po[0] = __half2(__float2half_rn(v.x), __float2half_rn(v.y));
    po[1] = __half2(__float2half_rn(v.z), __float2half_rn(v.w));
}

// Combine split-K partials -> single fp16 M
__global__ void combine_f16_kernel(__half* __restrict__ mh)
{
    const int idx = blockIdx.x * blockDim.x + threadIdx.x;
    if (idx >= DIM * DIM / 4) return;
    const int c = idx << 2;
    float4 a = *reinterpret_cast<const float4*>(g_p0 + c);
    float4 b = *reinterpret_cast<const float4*>(g_p1 + c);
    __half2* pm = reinterpret_cast<__half2*>(mh + c);
    pm[0] = __half2(__float2half_rn(a.x + b.x), __float2half_rn(a.y + b.y));
    pm[1] = __half2(__float2half_rn(a.z + b.z), __float2half_rn(a.w + b.w));
}

// ---------------------------------------------------------------------------
// Plain fp16 HMMA GEMM:  C[M,N] = A[M,K] @ B[K,N] (+ bias)
// CTA tile 128x128, 8 warps of 64x32, KC=64, cp.async 3-stage, 2 CTA/SM.
// Split-K via blockIdx.z (window z*K..(z+1)*K, output Cf / Cf1, fp32).
// ---------------------------------------------------------------------------
constexpr int BN = 128, KC = 64;
constexpr int NSTAGE = 3;
constexpr int APITCH = 144;                 // 128B data + 16B pad
constexpr int BPITCH = 272;                 // 256B data + 16B pad
constexpr int B_BYTES = KC * BPITCH;        // 17408
constexpr int A_BYTES = 128 * APITCH;       // 18432
constexpr int STAGE_BYTES = A_BYTES + B_BYTES;
constexpr int SMEMT = NSTAGE * STAGE_BYTES; // 107520 -> 2 CTA/SM

__device__ __forceinline__ void issue_chunk(
    uint32_t sbase, int st,
    const __half* Aptr, const __half* Bptr,
    int lda, int ldb, int m0, int n0, int k0, int tid)
{
    const uint32_t sA = sbase + st * STAGE_BYTES;
    const uint32_t sB = sA + A_BYTES;
    const int arow = tid >> 3, ack = tid & 7;
    const int brow = tid >> 4, bck = tid & 15;
    #pragma unroll
    for (int p = 0; p < 4; p++) {
        const int r = arow + p * 32;
        cp16(sA + r * APITCH + ack * 16,
             Aptr + (size_t)(m0 + r) * lda + k0 + ack * 8);
        const int kr = brow + p * 16;
        cp16(sB + kr * BPITCH + bck * 16,
             Bptr + (size_t)(k0 + kr) * ldb + n0 + bck * 8);
    }
    CP_COMMIT();
}

__global__ __launch_bounds__(256, 2)
void gemm_f16(const __half* __restrict__ A, int lda,
              const __half* __restrict__ B, int ldb,
              float* __restrict__ Cf, float* __restrict__ Cf1,
              const float* __restrict__ bias,
              int ldc, int K)
{
    extern __shared__ char smem[];
    const uint32_t sbase = smem_u32(smem);
    const int tid  = threadIdx.x;
    const int wid  = tid >> 5;
    const int lane = tid & 31;
    const int wr   = wid >> 2;     // 0..1  (warp row: 64 rows each)
    const int wc   = wid & 3;      // 0..3  (warp col: 32 cols each)
    const int m0   = blockIdx.y * 128;
    const int n0   = blockIdx.x * BN;
    const int z    = blockIdx.z;   // split-K index

    A += (size_t)z * K;            // shift K window (columns of A)
    B += (size_t)z * K * ldb;      // shift K window (rows of B)
    float* Csel = (z == 0) ? Cf : Cf1;

    const int NCH = K / KC;

    float d[4][4][4];
    #pragma unroll
    for (int mi = 0; mi < 4; mi++)
        #pragma unroll
        for (int ni = 0; ni < 4; ni++)
            #pragma unroll
            for (int r = 0; r < 4; r++) d[mi][ni][r] = 0.0f;

    // Prologue: stages 0, 1
    #pragma unroll
    for (int s = 0; s < NSTAGE - 1; s++)
        issue_chunk(sbase, s, A, B, lda, ldb, m0, n0, s * KC, tid);

    for (int ch = 0; ch < NCH; ch++) {
        if (ch + 2 < NCH)
            issue_chunk(sbase, (ch + 2) % NSTAGE, A, B, lda, ldb, m0, n0, (ch + 2) * KC, tid);
        if (ch + 2 < NCH)       asm volatile("cp.async.wait_group 2;" ::: "memory");
        else if (ch + 1 < NCH)  asm volatile("cp.async.wait_group 1;" ::: "memory");
        else                    asm volatile("cp.async.wait_group 0;" ::: "memory");
        __syncthreads();

        const uint32_t sA = sbase + (ch % NSTAGE) * STAGE_BYTES;
        const uint32_t sB = sA + A_BYTES;

        #pragma unroll
        for (int ki = 0; ki < KC / 16; ki++) {
            uint32_t a[4][4];
            #pragma unroll
            for (int mi = 0; mi < 4; mi++) {
                const uint32_t addr = sA
                    + (uint32_t)(wr * 64 + mi * 16 + (lane & 15)) * APITCH
                    + (uint32_t)((lane >> 4) * 8 + ki * 16) * 2;
                asm volatile("ldmatrix.sync.aligned.m8n8.x4.shared.b16 {%0,%1,%2,%3}, [%4];"
                    : "=r"(a[mi][0]), "=r"(a[mi][1]), "=r"(a[mi][2]), "=r"(a[mi][3])
                    : "r"(addr));
            }
            uint32_t b[4][2];
            #pragma unroll
            for (int t = 0; t < 2; t++) {
                const uint32_t addr = sB
                    + (uint32_t)(ki * 16 + (lane & 15)) * BPITCH
                    + (uint32_t)(wc * 32 + t * 16 + (lane >> 4) * 8) * 2;
                uint32_t r0, r1, r2, r3;
                asm volatile("ldmatrix.sync.aligned.m8n8.x4.trans.shared.b16 {%0,%1,%2,%3}, [%4];"
                    : "=r"(r0), "=r"(r1), "=r"(r2), "=r"(r3) : "r"(addr));
                b[2 * t][0] = r0;  b[2 * t][1] = r1;
                b[2 * t + 1][0] = r2;  b[2 * t + 1][1] = r3;
            }
            #pragma unroll
            for (int mi = 0; mi < 4; mi++)
                #pragma unroll
                for (int ni = 0; ni < 4; ni++)
                    mma_f16(d[mi][ni], a[mi], b[ni]);
        }
        __syncthreads();
    }

    // ---- Epilogue: fp32 output (+ optional bias) ----
    #pragma unroll
    for (int mi = 0; mi < 4; mi++) {
        const int mrow = m0 + wr * 64 + mi * 16 + (lane >> 2);
        #pragma unroll
        for (int ni = 0; ni < 4; ni++) {
            const int ncol = n0 + wc * 32 + ni * 8 + (lane & 3) * 2;
            #pragma unroll
            for (int half = 0; half < 2; half++) {
                const int r = mrow + half * 8;
                float v0 = d[mi][ni][half * 2 + 0];
                float v1 = d[mi][ni][half * 2 + 1];
                if (bias != nullptr) { v0 += bias[ncol]; v1 += bias[ncol + 1]; }
                float2 o; o.x = v0; o.y = v1;
                *reinterpret_cast<float2*>(Csel + (size_t)r * ldc + ncol) = o;
            }
        }
    }
}

// ---------------------------------------------------------------------------
// Fused bias, parallel: c[j] = sum_k b_v[k] * w_proj[k, j] + b_proj[j]
// ---------------------------------------------------------------------------
__global__ void bias_partial_kernel(const float* __restrict__ b_qkv,
                                    const float* __restrict__ w_proj)
{
    const int j  = blockIdx.x * blockDim.x + threadIdx.x;
    const int s  = blockIdx.y;
    const int kb = s * (DIM / KSLICES);
    float acc = 0.0f;
    #pragma unroll
    for (int k = 0; k < DIM / KSLICES; k++)
        acc += b_qkv[2 * DIM + kb + k] * w_proj[(size_t)(kb + k) * DIM + j];
    g_cpart[s * DIM + j] = acc;
}

__global__ void bias_reduce_kernel(const float* __restrict__ b_proj)
{
    const int j = blockIdx.x * blockDim.x + threadIdx.x;
    if (j >= DIM) return;
    float acc = b_proj[j];
    #pragma unroll 16
    for (int s = 0; s < KSLICES; s++) acc += g_cpart[s * DIM + j];
    g_c[j] = acc;
}

// ---------------------------------------------------------------------------
// kernel_launch  (captured fork/join streams)
// Math: softmax rows sum to 1 and the reference's final einsum contracts k
// over attn only, so out == v. Head permutations cancel on flattened layout:
//   out = x @ (w_qkv[:,2C:3C] @ w_proj) + (b_qkv[2C:3C] @ w_proj + b_proj)
//
// Stream layout:
//   main(0): cvt weights -> GEMM1 (split-K) -> combine  ┐
//   s1     : cvt x                                       ├-> GEMM2
//   s2     : bias partial -> bias reduce                 ┘
// ---------------------------------------------------------------------------
extern "C" void kernel_launch(void* const* d_in, const int* in_sizes, int n_in,
                              void* d_out, int out_size)
{
    const float* x      = (const float*)d_in[0];  // [4096, 1024]
    const float* w_qkv  = (const float*)d_in[1];  // [1024, 3072]
    const float* b_qkv  = (const float*)d_in[2];  // [3072]
    const float* w_proj = (const float*)d_in[3];  // [1024, 1024]
    const float* b_proj = (const float*)d_in[4];  // [1024]
    float* out = (float*)d_out;                   // [4096, 1024]

    __half *xh, *wv, *wp, *mh;
    float *pc, *p0, *p1;
    cudaGetSymbolAddress((void**)&xh, g_xh);
    cudaGetSymbolAddress((void**)&wv, g_wv);
    cudaGetSymbolAddress((void**)&wp, g_wp);
    cudaGetSymbolAddress((void**)&mh, g_mh);
    cudaGetSymbolAddress((void**)&pc, g_c);
    cudaGetSymbolAddress((void**)&p0, g_p0);
    cudaGetSymbolAddress((void**)&p1, g_p1);

    // One-time host-side setup (no device memory).
    static cudaStream_t s1 = nullptr, s2 = nullptr;
    static cudaEvent_t ev0, ev1, ev2;
    if (s1 == nullptr) {
        cudaStreamCreateWithFlags(&s1, cudaStreamNonBlocking);
        cudaStreamCreateWithFlags(&s2, cudaStreamNonBlocking);
        cudaEventCreateWithFlags(&ev0, cudaEventDisableTiming);
        cudaEventCreateWithFlags(&ev1, cudaEventDisableTiming);
        cudaEventCreateWithFlags(&ev2, cudaEventDisableTiming);
        cudaFuncSetAttribute(gemm_f16, cudaFuncAttributeMaxDynamicSharedMemorySize, SMEMT);
    }

    // Fork
    cudaEventRecord(ev0, 0);
    cudaStreamWaitEvent(s1, ev0, 0);
    cudaStreamWaitEvent(s2, ev0, 0);

    // s1: x convert (independent)
    cvt_f16_kernel<<<(ROWS * DIM / 4 + 255) / 256, 256, 0, s1>>>(x, DIM, xh, ROWS, DIM);
    cudaEventRecord(ev1, s1);

    // s2: bias chain (independent)
    {
        dim3 grid(DIM / 256, KSLICES);
        bias_partial_kernel<<<grid, 256, 0, s2>>>(b_qkv, w_proj);
        bias_reduce_kernel<<<DIM / 256, 256, 0, s2>>>(b_proj);
    }
    cudaEventRecord(ev2, s2);

    // main: weight converts (one launch) -> GEMM1 -> combine
    cvt_weights_kernel<<<(2 * DIM * DIM / 4 + 255) / 256, 256>>>(w_qkv, w_proj, wv, wp);
    {
        dim3 grid(DIM / BN, DIM / 128, 2);   // 8 x 8 x 2
        gemm_f16<<<grid, 256, SMEMT>>>(wv, DIM, wp, DIM, p0, p1, nullptr, DIM, DIM / 2);
    }
    combine_f16_kernel<<<(DIM * DIM / 4 + 255) / 256, 256>>>(mh);

    // Join
    cudaStreamWaitEvent(0, ev1, 0);
    cudaStreamWaitEvent(0, ev2, 0);

    // GEMM2: out = x16 @ M16 + c   (plain fp16, 16 chunks)
    {
        dim3 grid(DIM / BN, ROWS / 128, 1);  // 8 x 32
        gemm_f16<<<grid, 256, SMEMT>>>(xh, DIM, mh, DIM, out, nullptr, pc, DIM, DIM);
    }
}

// round 17
// speedup vs baseline: 2.6597x; 1.0377x over previous
#include <cuda_runtime.h>
#include <cuda_fp16.h>
#include <cstdint>

// ---------------------------------------------------------------------------
// Problem constants
// ---------------------------------------------------------------------------
constexpr int DIM  = 1024;
constexpr int ROWS = 4096;   // BATCH * SEQ

// ---------------------------------------------------------------------------
// Device scratch (allocation-free per harness rules)
// All GEMM operands rounded to fp16. Four independent rounding sources
// (Wv, Wp, M, x), each ~2.08e-4 empirical rel_err, quadrature ~4.2e-4.
// ---------------------------------------------------------------------------
__device__ __align__(16) __half g_xh[ROWS * DIM];
__device__ __align__(16) __half g_wv[DIM * DIM];
__device__ __align__(16) __half g_wp[DIM * DIM];
__device__ __align__(16) __half g_mh[DIM * DIM];   // M = Wv @ Wp (fp16)
__device__ __align__(16) float g_p0[DIM * DIM];    // split-K partial 0
__device__ __align__(16) float g_p1[DIM * DIM];    // split-K partial 1
__device__ float g_c[DIM];                          // fused bias
constexpr int KSLICES = 64;
__device__ float g_cpart[KSLICES * DIM];            // bias partials

// ---------------------------------------------------------------------------
// Helpers
// ---------------------------------------------------------------------------
__device__ __forceinline__ uint32_t smem_u32(const void* p) {
    uint32_t a;
    asm("{ .reg .u64 t; cvta.to.shared.u64 t, %1; cvt.u32.u64 %0, t; }" : "=r"(a) : "l"(p));
    return a;
}
__device__ __forceinline__ void cp16(uint32_t dst, const void* src) {
    asm volatile("cp.async.cg.shared.global [%0], [%1], 16;" :: "r"(dst), "l"(src));
}
#define CP_COMMIT() asm volatile("cp.async.commit_group;" ::: "memory")

__device__ __forceinline__ void mma_f16(float d[4], const uint32_t a[4], const uint32_t b[2]) {
    asm volatile(
        "mma.sync.aligned.m16n8k16.row.col.f32.f16.f16.f32 "
        "{%0,%1,%2,%3}, {%4,%5,%6,%7}, {%8,%9}, {%0,%1,%2,%3};"
        : "+f"(d[0]), "+f"(d[1]), "+f"(d[2]), "+f"(d[3])
        : "r"(a[0]), "r"(a[1]), "r"(a[2]), "r"(a[3]), "r"(b[0]), "r"(b[1]));
}

// ---------------------------------------------------------------------------
// Conversion kernels
// ---------------------------------------------------------------------------
__global__ void cvt_f16_kernel(const float* __restrict__ in, int ld,
                               __half* __restrict__ out16,
                               int rows, int cols)
{
    const int idx = blockIdx.x * blockDim.x + threadIdx.x;
    const int c4 = cols >> 2;
    if (idx >= rows * c4) return;
    const int r = idx / c4;
    const int c = (idx - r * c4) << 2;
    float4 v = *reinterpret_cast<const float4*>(in + (size_t)r * ld + c);
    __half2* po = reinterpret_cast<__half2*>(out16 + (size_t)r * cols + c);
    po[0] = __half2(__float2half_rn(v.x), __float2half_rn(v.y));
    po[1] = __half2(__float2half_rn(v.z), __float2half_rn(v.w));
}

// Both weight matrices in one launch: half the grid does Wv, half Wp.
__global__ void cvt_weights_kernel(const float* __restrict__ w_qkv,
                                   const float* __restrict__ w_proj,
                                   __half* __restrict__ wv,
                                   __half* __restrict__ wp)
{
    const int n4 = DIM * DIM / 4;
    int idx = blockIdx.x * blockDim.x + threadIdx.x;
    const float* in;  int ld;  __half* out16;
    if (idx < n4) {
        in = w_qkv + 2 * DIM;  ld = 3 * DIM;  out16 = wv;
    } else {
        idx -= n4;
        if (idx >= n4) return;
        in = w_proj;  ld = DIM;  out16 = wp;
    }
    const int c4 = DIM >> 2;
    const int r = idx / c4;
    const int c = (idx - r * c4) << 2;
    float4 v = *reinterpret_cast<const float4*>(in + (size_t)r * ld + c);
    __half2* po = reinterpret_cast<__half2*>(out16 + (size_t)r * DIM + c);
    po[0] = __half2(__float2half_rn(v.x), __float2half_rn(v.y));
    po[1] = __half2(__float2half_rn(v.z), __float2half_rn(v.w));
}

// Combine split-K partials -> single fp16 M
__global__ void combine_f16_kernel(__half* __restrict__ mh)
{
    const int idx = blockIdx.x * blockDim.x + threadIdx.x;
    if (idx >= DIM * DIM / 4) return;
    const int c = idx << 2;
    float4 a = *reinterpret_cast<const float4*>(g_p0 + c);
    float4 b = *reinterpret_cast<const float4*>(g_p1 + c);
    __half2* pm = reinterpret_cast<__half2*>(mh + c);
    pm[0] = __half2(__float2half_rn(a.x + b.x), __float2half_rn(a.y + b.y));
    pm[1] = __half2(__float2half_rn(a.z + b.z), __float2half_rn(a.w + b.w));
}

// ---------------------------------------------------------------------------
// Plain fp16 HMMA GEMM:  C[M,N] = A[M,K] @ B[K,N] (+ bias)
// CTA tile 128x128, 8 warps of 64x32, KC=64, cp.async 3-stage, 2 CTA/SM.
// Fragment double-buffering across ki: ldmatrix for ki+1 issued before the
// MMAs of ki, hiding LDS latency under the tensor pipe.
// Split-K via blockIdx.z (window z*K..(z+1)*K, output Cf / Cf1, fp32).
// ---------------------------------------------------------------------------
constexpr int BN = 128, KC = 64;
constexpr int NSTAGE = 3;
constexpr int APITCH = 144;                 // 128B data + 16B pad
constexpr int BPITCH = 272;                 // 256B data + 16B pad
constexpr int B_BYTES = KC * BPITCH;        // 17408
constexpr int A_BYTES = 128 * APITCH;       // 18432
constexpr int STAGE_BYTES = A_BYTES + B_BYTES;
constexpr int SMEMT = NSTAGE * STAGE_BYTES; // 107520 -> 2 CTA/SM

__device__ __forceinline__ void issue_chunk(
    uint32_t sbase, int st,
    const __half* Aptr, const __half* Bptr,
    int lda, int ldb, int m0, int n0, int k0, int tid)
{
    const uint32_t sA = sbase + st * STAGE_BYTES;
    const uint32_t sB = sA + A_BYTES;
    const int arow = tid >> 3, ack = tid & 7;
    const int brow = tid >> 4, bck = tid & 15;
    #pragma unroll
    for (int p = 0; p < 4; p++) {
        const int r = arow + p * 32;
        cp16(sA + r * APITCH + ack * 16,
             Aptr + (size_t)(m0 + r) * lda + k0 + ack * 8);
        const int kr = brow + p * 16;
        cp16(sB + kr * BPITCH + bck * 16,
             Bptr + (size_t)(k0 + kr) * ldb + n0 + bck * 8);
    }
    CP_COMMIT();
}

__global__ __launch_bounds__(256, 2)
void gemm_f16(const __half* __restrict__ A, int lda,
              const __half* __restrict__ B, int ldb,
              float* __restrict__ Cf, float* __restrict__ Cf1,
              const float* __restrict__ bias,
              int ldc, int K)
{
    extern __shared__ char smem[];
    const uint32_t sbase = smem_u32(smem);
    const int tid  = threadIdx.x;
    const int wid  = tid >> 5;
    const int lane = tid & 31;
    const int wr   = wid >> 2;     // 0..1  (warp row: 64 rows each)
    const int wc   = wid & 3;      // 0..3  (warp col: 32 cols each)
    const int m0   = blockIdx.y * 128;
    const int n0   = blockIdx.x * BN;
    const int z    = blockIdx.z;   // split-K index

    A += (size_t)z * K;            // shift K window (columns of A)
    B += (size_t)z * K * ldb;      // shift K window (rows of B)
    float* Csel = (z == 0) ? Cf : Cf1;

    const int NCH = K / KC;

    float d[4][4][4];
    #pragma unroll
    for (int mi = 0; mi < 4; mi++)
        #pragma unroll
        for (int ni = 0; ni < 4; ni++)
            #pragma unroll
            for (int r = 0; r < 4; r++) d[mi][ni][r] = 0.0f;

    // Per-warp invariant pieces of the ldmatrix addresses
    const uint32_t aBase = (uint32_t)(wr * 64 + (lane & 15)) * APITCH
                         + (uint32_t)((lane >> 4) * 8) * 2;
    const uint32_t bBase = (uint32_t)(lane & 15) * BPITCH
                         + (uint32_t)(wc * 32 + (lane >> 4) * 8) * 2;

    // Prologue: stages 0, 1
    #pragma unroll
    for (int s = 0; s < NSTAGE - 1; s++)
        issue_chunk(sbase, s, A, B, lda, ldb, m0, n0, s * KC, tid);

    for (int ch = 0; ch < NCH; ch++) {
        if (ch + 2 < NCH)
            issue_chunk(sbase, (ch + 2) % NSTAGE, A, B, lda, ldb, m0, n0, (ch + 2) * KC, tid);
        if (ch + 2 < NCH)       asm volatile("cp.async.wait_group 2;" ::: "memory");
        else if (ch + 1 < NCH)  asm volatile("cp.async.wait_group 1;" ::: "memory");
        else                    asm volatile("cp.async.wait_group 0;" ::: "memory");
        __syncthreads();

        const uint32_t sA = sbase + (ch % NSTAGE) * STAGE_BYTES;
        const uint32_t sB = sA + A_BYTES;

        // Fragment loader for one ki step
        auto load_frags = [&](int ki, uint32_t a[4][4], uint32_t b[4][2]) {
            #pragma unroll
            for (int mi = 0; mi < 4; mi++) {
                const uint32_t addr = sA + aBase
                    + (uint32_t)(mi * 16) * APITCH
                    + (uint32_t)(ki * 16) * 2;
                asm volatile("ldmatrix.sync.aligned.m8n8.x4.shared.b16 {%0,%1,%2,%3}, [%4];"
                    : "=r"(a[mi][0]), "=r"(a[mi][1]), "=r"(a[mi][2]), "=r"(a[mi][3])
                    : "r"(addr));
            }
            #pragma unroll
            for (int t = 0; t < 2; t++) {
                const uint32_t addr = sB + bBase
                    + (uint32_t)(ki * 16) * BPITCH
                    + (uint32_t)(t * 16) * 2;
                uint32_t r0, r1, r2, r3;
                asm volatile("ldmatrix.sync.aligned.m8n8.x4.trans.shared.b16 {%0,%1,%2,%3}, [%4];"
                    : "=r"(r0), "=r"(r1), "=r"(r2), "=r"(r3) : "r"(addr));
                b[2 * t][0] = r0;      b[2 * t][1] = r1;
                b[2 * t + 1][0] = r2;  b[2 * t + 1][1] = r3;
            }
        };

        // Software-pipelined ki loop: double-buffered fragments
        uint32_t af[2][4][4];
        uint32_t bf[2][4][2];
        load_frags(0, af[0], bf[0]);
        #pragma unroll
        for (int ki = 0; ki < KC / 16; ki++) {
            const int cur = ki & 1;
            if (ki + 1 < KC / 16)
                load_frags(ki + 1, af[cur ^ 1], bf[cur ^ 1]);
            #pragma unroll
            for (int mi = 0; mi < 4; mi++)
                #pragma unroll
                for (int ni = 0; ni < 4; ni++)
                    mma_f16(d[mi][ni], af[cur][mi], bf[cur][ni]);
        }
        __syncthreads();
    }

    // ---- Epilogue: fp32 output (+ optional bias) ----
    #pragma unroll
    for (int mi = 0; mi < 4; mi++) {
        const int mrow = m0 + wr * 64 + mi * 16 + (lane >> 2);
        #pragma unroll
        for (int ni = 0; ni < 4; ni++) {
            const int ncol = n0 + wc * 32 + ni * 8 + (lane & 3) * 2;
            #pragma unroll
            for (int half = 0; half < 2; half++) {
                const int r = mrow + half * 8;
                float v0 = d[mi][ni][half * 2 + 0];
                float v1 = d[mi][ni][half * 2 + 1];
                if (bias != nullptr) { v0 += bias[ncol]; v1 += bias[ncol + 1]; }
                float2 o; o.x = v0; o.y = v1;
                *reinterpret_cast<float2*>(Csel + (size_t)r * ldc + ncol) = o;
            }
        }
    }
}

// ---------------------------------------------------------------------------
// Fused bias, parallel: c[j] = sum_k b_v[k] * w_proj[k, j] + b_proj[j]
// ---------------------------------------------------------------------------
__global__ void bias_partial_kernel(const float* __restrict__ b_qkv,
                                    const float* __restrict__ w_proj)
{
    const int j  = blockIdx.x * blockDim.x + threadIdx.x;
    const int s  = blockIdx.y;
    const int kb = s * (DIM / KSLICES);
    float acc = 0.0f;
    #pragma unroll
    for (int k = 0; k < DIM / KSLICES; k++)
        acc += b_qkv[2 * DIM + kb + k] * w_proj[(size_t)(kb + k) * DIM + j];
    g_cpart[s * DIM + j] = acc;
}

__global__ void bias_reduce_kernel(const float* __restrict__ b_proj)
{
    const int j = blockIdx.x * blockDim.x + threadIdx.x;
    if (j >= DIM) return;
    float acc = b_proj[j];
    #pragma unroll 16
    for (int s = 0; s < KSLICES; s++) acc += g_cpart[s * DIM + j];
    g_c[j] = acc;
}

// ---------------------------------------------------------------------------
// kernel_launch  (captured fork/join streams)
// Math: softmax rows sum to 1 and the reference's final einsum contracts k
// over attn only, so out == v. Head permutations cancel on flattened layout:
//   out = x @ (w_qkv[:,2C:3C] @ w_proj) + (b_qkv[2C:3C] @ w_proj + b_proj)
//
// Stream layout:
//   main(0): cvt weights -> GEMM1 (split-K) -> combine  ┐
//   s1     : cvt x                                       ├-> GEMM2
//   s2     : bias partial -> bias reduce                 ┘
// ---------------------------------------------------------------------------
extern "C" void kernel_launch(void* const* d_in, const int* in_sizes, int n_in,
                              void* d_out, int out_size)
{
    const float* x      = (const float*)d_in[0];  // [4096, 1024]
    const float* w_qkv  = (const float*)d_in[1];  // [1024, 3072]
    const float* b_qkv  = (const float*)d_in[2];  // [3072]
    const float* w_proj = (const float*)d_in[3];  // [1024, 1024]
    const float* b_proj = (const float*)d_in[4];  // [1024]
    float* out = (float*)d_out;                   // [4096, 1024]

    __half *xh, *wv, *wp, *mh;
    float *pc, *p0, *p1;
    cudaGetSymbolAddress((void**)&xh, g_xh);
    cudaGetSymbolAddress((void**)&wv, g_wv);
    cudaGetSymbolAddress((void**)&wp, g_wp);
    cudaGetSymbolAddress((void**)&mh, g_mh);
    cudaGetSymbolAddress((void**)&pc, g_c);
    cudaGetSymbolAddress((void**)&p0, g_p0);
    cudaGetSymbolAddress((void**)&p1, g_p1);

    // One-time host-side setup (no device memory).
    static cudaStream_t s1 = nullptr, s2 = nullptr;
    static cudaEvent_t ev0, ev1, ev2;
    if (s1 == nullptr) {
        cudaStreamCreateWithFlags(&s1, cudaStreamNonBlocking);
        cudaStreamCreateWithFlags(&s2, cudaStreamNonBlocking);
        cudaEventCreateWithFlags(&ev0, cudaEventDisableTiming);
        cudaEventCreateWithFlags(&ev1, cudaEventDisableTiming);
        cudaEventCreateWithFlags(&ev2, cudaEventDisableTiming);
        cudaFuncSetAttribute(gemm_f16, cudaFuncAttributeMaxDynamicSharedMemorySize, SMEMT);
    }

    // Fork
    cudaEventRecord(ev0, 0);
    cudaStreamWaitEvent(s1, ev0, 0);
    cudaStreamWaitEvent(s2, ev0, 0);

    // s1: x convert (independent)
    cvt_f16_kernel<<<(ROWS * DIM / 4 + 255) / 256, 256, 0, s1>>>(x, DIM, xh, ROWS, DIM);
    cudaEventRecord(ev1, s1);

    // s2: bias chain (independent)
    {
        dim3 grid(DIM / 256, KSLICES);
        bias_partial_kernel<<<grid, 256, 0, s2>>>(b_qkv, w_proj);
        bias_reduce_kernel<<<DIM / 256, 256, 0, s2>>>(b_proj);
    }
    cudaEventRecord(ev2, s2);

    // main: weight converts (one launch) -> GEMM1 -> combine
    cvt_weights_kernel<<<(2 * DIM * DIM / 4 + 255) / 256, 256>>>(w_qkv, w_proj, wv, wp);
    {
        dim3 grid(DIM / BN, DIM / 128, 2);   // 8 x 8 x 2
        gemm_f16<<<grid, 256, SMEMT>>>(wv, DIM, wp, DIM, p0, p1, nullptr, DIM, DIM / 2);
    }
    combine_f16_kernel<<<(DIM * DIM / 4 + 255) / 256, 256>>>(mh);

    // Join
    cudaStreamWaitEvent(0, ev1, 0);
    cudaStreamWaitEvent(0, ev2, 0);

    // GEMM2: out = x16 @ M16 + c   (plain fp16, 16 chunks)
    {
        dim3 grid(DIM / BN, ROWS / 128, 1);  // 8 x 32
        gemm_f16<<<grid, 256, SMEMT>>>(xh, DIM, mh, DIM, out, nullptr, pc, DIM, DIM);
    }
}